// round 11
// baseline (speedup 1.0000x reference)
#include <cuda_runtime.h>
#include <cuda_fp16.h>
#include <math.h>
#include <stdint.h>

#define DT 0.01f
#define TWO_PI 6.28318530717958647692f

#define BSZ 4096
#define DSZ 2048
#define NSZ 4096

// scan chunking
#define CCH 256
#define LCH (BSZ / CCH)   // 16

// GEMM tiling
#define GBM 128
#define GBN 128
#define GBK 32                    // fp16 elems per stage (two k16 micro-steps)
#define ROWB 80                   // padded smem row bytes (64B data + 16B pad)
#define TILEB (128 * ROWB)        // 10240 bytes per matrix tile
#define STAGEB (2 * TILEB)        // A, B
#define NSTG 3
#define KITERS (DSZ / GBK)        // 64
#define PIPE_BYTES (NSTG * STAGEB)        // 61440
#define EPI_BYTES (128 * 129 * 4)         // 66048 (column-major tile, pad 129)
#define SMEM_BYTES (EPI_BYTES > PIPE_BYTES ? EPI_BYTES : PIPE_BYTES)

// ---------------- static device scratch (no allocations allowed) -----------
__device__ __half g_Ah[(size_t)BSZ * DSZ];
__device__ __half g_Wh[(size_t)NSZ * DSZ];
__device__ float g_force[(size_t)BSZ * NSZ];
__device__ float g_cs[(size_t)CCH * NSZ], g_cv[(size_t)CCH * NSZ];
__device__ float g_zs[(size_t)CCH * NSZ], g_zv[(size_t)CCH * NSZ];

// ---------------- helpers --------------------------------------------------
__device__ __forceinline__ uint32_t smem_u32(const void* p) {
    uint32_t a;
    asm("{ .reg .u64 t; cvta.to.shared.u64 t, %1; cvt.u32.u64 %0, t; }" : "=r"(a) : "l"(p));
    return a;
}
__device__ __forceinline__ void cp16(uint32_t dst, const void* src) {
    asm volatile("cp.async.cg.shared.global [%0], [%1], 16;\n" :: "r"(dst), "l"(src));
}
__device__ __forceinline__ void ldsm_x4(uint32_t* r, uint32_t addr) {
    asm volatile("ldmatrix.sync.aligned.m8n8.x4.shared.b16 {%0,%1,%2,%3}, [%4];"
                 : "=r"(r[0]), "=r"(r[1]), "=r"(r[2]), "=r"(r[3]) : "r"(addr));
}
__device__ __forceinline__ void mma_f16(float* d, const uint32_t* a, const uint32_t* b) {
    asm volatile(
        "mma.sync.aligned.m16n8k16.row.col.f32.f16.f16.f32 "
        "{%0,%1,%2,%3}, {%4,%5,%6,%7}, {%8,%9}, {%0,%1,%2,%3};"
        : "+f"(d[0]), "+f"(d[1]), "+f"(d[2]), "+f"(d[3])
        : "r"(a[0]), "r"(a[1]), "r"(a[2]), "r"(a[3]), "r"(b[0]), "r"(b[1]));
}

// ---------------- convert kernels: fp32 -> fp16 ----------------------------
__global__ __launch_bounds__(256) void cvtA_kernel(const float* __restrict__ src) {
    size_t i = (size_t)blockIdx.x * 256 + threadIdx.x;
    float4 a = reinterpret_cast<const float4*>(src)[i];
    __half2 lo = __floats2half2_rn(a.x, a.y);
    __half2 hi = __floats2half2_rn(a.z, a.w);
    uint2 o;
    o.x = *reinterpret_cast<uint32_t*>(&lo);
    o.y = *reinterpret_cast<uint32_t*>(&hi);
    reinterpret_cast<uint2*>(g_Ah)[i] = o;
}
__global__ __launch_bounds__(256) void cvtW_kernel(const float* __restrict__ src) {
    size_t i = (size_t)blockIdx.x * 256 + threadIdx.x;
    float4 a = reinterpret_cast<const float4*>(src)[i];
    __half2 lo = __floats2half2_rn(a.x, a.y);
    __half2 hi = __floats2half2_rn(a.z, a.w);
    uint2 o;
    o.x = *reinterpret_cast<uint32_t*>(&lo);
    o.y = *reinterpret_cast<uint32_t*>(&hi);
    reinterpret_cast<uint2*>(g_Wh)[i] = o;
}

// ---------------- fp16 mma.sync GEMM + fused chunk-carry scan -------------
struct Frag {
    uint32_t a[4][4];
    uint32_t b[2][4];
};

__global__ __launch_bounds__(256, 1) void gemm_f16_kernel(
    const float* __restrict__ bias,
    const float* __restrict__ freq,
    const float* __restrict__ damp) {
    extern __shared__ char smem_raw[];
    const uint32_t sbase = smem_u32(smem_raw);
    const int tid = threadIdx.x;
    const int lane = tid & 31;
    const int wid = tid >> 5;
    const int m0 = blockIdx.y * GBM;
    const int n0 = blockIdx.x * GBN;
    const int wm = (wid >> 2) * 64;   // 2 warp rows
    const int wn = (wid & 3) * 32;    // 4 warp cols

    float acc[4][4][4];
    #pragma unroll
    for (int mt = 0; mt < 4; ++mt)
        #pragma unroll
        for (int nt = 0; nt < 4; ++nt)
            #pragma unroll
            for (int r = 0; r < 4; ++r)
                acc[mt][nt][r] = 0.0f;

    const uint32_t a_row_off = (uint32_t)(wm + (lane & 15)) * ROWB;
    const uint32_t a_csel = ((lane >> 4) & 1) * 16;
    const uint32_t b_row_off = (uint32_t)(wn + ((lane >> 4) & 1) * 8 + (lane & 7)) * ROWB;
    const uint32_t b_csel = ((lane >> 3) & 1) * 16;

    auto load_stage = [&](int s, int buf) {
        uint32_t sb = sbase + (uint32_t)buf * STAGEB;
        int k0 = s * GBK;
        #pragma unroll
        for (int it = 0; it < 2; ++it) {
            int c = tid + it * 256;
            int row = c >> 2, c16 = c & 3;
            uint32_t soff = (uint32_t)row * ROWB + (uint32_t)c16 * 16;
            size_t gA = (size_t)(m0 + row) * DSZ + k0 + c16 * 8;
            size_t gB = (size_t)(n0 + row) * DSZ + k0 + c16 * 8;
            cp16(sb + soff, g_Ah + gA);
            cp16(sb + TILEB + soff, g_Wh + gB);
        }
    };

    auto load_frags = [&](Frag& f, uint32_t sb, int ks) {
        const uint32_t acol = (uint32_t)(ks * 32) + a_csel;
        const uint32_t bcol = (uint32_t)(ks * 32) + b_csel;
        #pragma unroll
        for (int mt = 0; mt < 4; ++mt)
            ldsm_x4(f.a[mt], sb + a_row_off + (uint32_t)(mt * 16) * ROWB + acol);
        #pragma unroll
        for (int p = 0; p < 2; ++p)
            ldsm_x4(f.b[p], sb + TILEB + b_row_off + (uint32_t)(p * 16) * ROWB + bcol);
    };

    auto mma_all = [&](const Frag& f) {
        #pragma unroll
        for (int mt = 0; mt < 4; ++mt)
            #pragma unroll
            for (int p = 0; p < 2; ++p)
                #pragma unroll
                for (int h = 0; h < 2; ++h)
                    mma_f16(acc[mt][p * 2 + h], f.a[mt], &f.b[p][h * 2]);
    };

    // prologue: stages 0 and 1 in flight
    load_stage(0, 0);
    asm volatile("cp.async.commit_group;\n" ::: "memory");
    load_stage(1, 1);
    asm volatile("cp.async.commit_group;\n" ::: "memory");
    asm volatile("cp.async.wait_group 1;\n" ::: "memory");
    __syncthreads();

    Frag fa, fb;
    load_frags(fa, sbase, 0);

    for (int s = 0; s < KITERS; ++s) {
        const uint32_t sb_cur = sbase + (uint32_t)(s % NSTG) * STAGEB;
        if (s + 2 < KITERS) {
            load_stage(s + 2, (s + 2) % NSTG);
            asm volatile("cp.async.commit_group;\n" ::: "memory");
        }
        load_frags(fb, sb_cur, 1);
        mma_all(fa);

        if (s + 1 < KITERS) {
            if (s + 2 < KITERS)
                asm volatile("cp.async.wait_group 1;\n" ::: "memory");
            else
                asm volatile("cp.async.wait_group 0;\n" ::: "memory");
            __syncthreads();
            load_frags(fa, sbase + (uint32_t)((s + 1) % NSTG) * STAGEB, 0);
        }
        mma_all(fb);
    }

    // ---- epilogue: bias, write force (gmem) + stage tile into smem -------
    __syncthreads();   // all smem pipeline reads complete; safe to repurpose
    float* sf = reinterpret_cast<float*>(smem_raw);   // [col * 129 + row]

    #pragma unroll
    for (int nt = 0; nt < 4; ++nt) {
        int cl = wn + nt * 8 + (lane & 3) * 2;        // local col
        int c = n0 + cl;
        float b0 = __ldg(&bias[c]);
        float b1 = __ldg(&bias[c + 1]);
        #pragma unroll
        for (int mt = 0; mt < 4; ++mt) {
            int rl = wm + mt * 16 + (lane >> 2);      // local row
            int r = m0 + rl;
            float2 lo = make_float2(acc[mt][nt][0] + b0, acc[mt][nt][1] + b1);
            float2 hi = make_float2(acc[mt][nt][2] + b0, acc[mt][nt][3] + b1);
            *reinterpret_cast<float2*>(&g_force[(size_t)r * NSZ + c]) = lo;
            *reinterpret_cast<float2*>(&g_force[(size_t)(r + 8) * NSZ + c]) = hi;
            sf[cl * 129 + rl] = lo.x;
            sf[(cl + 1) * 129 + rl] = lo.y;
            sf[cl * 129 + rl + 8] = hi.x;
            sf[(cl + 1) * 129 + rl + 8] = hi.y;
        }
    }
    __syncthreads();

    // ---- fused scanA: per-(chunk, col) zero-init scan over 16 rows -------
    // 8 chunks x 128 cols = 1024 items; 256 threads x 4 items.
    #pragma unroll
    for (int it = 0; it < 4; ++it) {
        int item = tid + it * 256;
        int cl = item & 127;
        int chunk = item >> 7;                        // 0..7
        int n = n0 + cl;
        float f = __ldg(&freq[n]);
        float dmp = __ldg(&damp[n]);
        float w2 = (TWO_PI * f) * (TWO_PI * f);
        const float* col = sf + cl * 129 + chunk * LCH;
        float s = 0.0f, v = 0.0f;
        #pragma unroll
        for (int k = 0; k < LCH; ++k) {
            float accel = fmaf(-w2, s, fmaf(-dmp, v, col[k]));
            v = fmaf(accel, DT, v);
            s = fmaf(v, DT, s);
        }
        int gchunk = blockIdx.y * 8 + chunk;
        g_cs[(size_t)gchunk * NSZ + n] = s;
        g_cv[(size_t)gchunk * NSZ + n] = v;
    }
}

// ---------------- combine: z_{j+1} = M^L z_j + carry_j --------------------
__global__ __launch_bounds__(256) void combine_kernel(const float* __restrict__ freq,
                                                      const float* __restrict__ damp) {
    int n = blockIdx.x * 256 + threadIdx.x;
    float f = freq[n], dmp = damp[n];
    float w2 = (TWO_PI * f) * (TWO_PI * f);
    float b00 = 1.0f - w2 * DT * DT;
    float b01 = DT * (1.0f - dmp * DT);
    float b10 = -w2 * DT;
    float b11 = 1.0f - dmp * DT;
    float e00 = 1.0f, e01 = 0.0f, e10 = 0.0f, e11 = 1.0f;
    int p = LCH;
    while (p) {
        if (p & 1) {
            float t00 = b00 * e00 + b01 * e10, t01 = b00 * e01 + b01 * e11;
            float t10 = b10 * e00 + b11 * e10, t11 = b10 * e01 + b11 * e11;
            e00 = t00; e01 = t01; e10 = t10; e11 = t11;
        }
        float s00 = b00 * b00 + b01 * b10, s01 = b00 * b01 + b01 * b11;
        float s10 = b10 * b00 + b11 * b10, s11 = b10 * b01 + b11 * b11;
        b00 = s00; b01 = s01; b10 = s10; b11 = s11;
        p >>= 1;
    }
    float sz = 0.0f, vz = 0.0f;
    for (int j = 0; j < CCH; ++j) {
        g_zs[(size_t)j * NSZ + n] = sz;
        g_zv[(size_t)j * NSZ + n] = vz;
        float cs = g_cs[(size_t)j * NSZ + n], cv = g_cv[(size_t)j * NSZ + n];
        float ns = e00 * sz + e01 * vz + cs;
        float nv = e10 * sz + e11 * vz + cv;
        sz = ns; vz = nv;
    }
}

// ---------------- scan phase B: full scan from z, + osc, clip, write ------
__global__ __launch_bounds__(256) void scanB_kernel(const float* __restrict__ freq,
                                                    const float* __restrict__ damp,
                                                    const float* __restrict__ amp,
                                                    const float* __restrict__ phase,
                                                    float* __restrict__ out) {
    int c4 = blockIdx.x * 256 + threadIdx.x;
    int j = blockIdx.y;
    int n = c4 * 4;
    float4 f4 = *reinterpret_cast<const float4*>(freq + n);
    float4 d4 = *reinterpret_cast<const float4*>(damp + n);
    float4 a4 = *reinterpret_cast<const float4*>(amp + n);
    float4 p4 = *reinterpret_cast<const float4*>(phase + n);
    float wx = (TWO_PI * f4.x) * (TWO_PI * f4.x);
    float wy = (TWO_PI * f4.y) * (TWO_PI * f4.y);
    float wz = (TWO_PI * f4.z) * (TWO_PI * f4.z);
    float ww = (TWO_PI * f4.w) * (TWO_PI * f4.w);
    float ox = a4.x * sinf(fmaf(TWO_PI * f4.x, DT, p4.x));
    float oy = a4.y * sinf(fmaf(TWO_PI * f4.y, DT, p4.y));
    float oz = a4.z * sinf(fmaf(TWO_PI * f4.z, DT, p4.z));
    float ow = a4.w * sinf(fmaf(TWO_PI * f4.w, DT, p4.w));
    float4 zs = *reinterpret_cast<const float4*>(g_zs + (size_t)j * NSZ + n);
    float4 zv = *reinterpret_cast<const float4*>(g_zv + (size_t)j * NSZ + n);
    float sx = zs.x, sy = zs.y, szz = zs.z, sww = zs.w;
    float vx = zv.x, vy = zv.y, vzz = zv.z, vww = zv.w;
    const float4* fp = reinterpret_cast<const float4*>(g_force + (size_t)j * LCH * NSZ + n);
    float4* op = reinterpret_cast<float4*>(out + (size_t)j * LCH * NSZ + n);
    #pragma unroll
    for (int k = 0; k < LCH; ++k) {
        float4 fr = fp[(size_t)k * (NSZ / 4)];
        float ax = fmaf(-wx, sx, fmaf(-d4.x, vx, fr.x)); vx = fmaf(ax, DT, vx); sx = fmaf(vx, DT, sx);
        float ay = fmaf(-wy, sy, fmaf(-d4.y, vy, fr.y)); vy = fmaf(ay, DT, vy); sy = fmaf(vy, DT, sy);
        float az = fmaf(-wz, szz, fmaf(-d4.z, vzz, fr.z)); vzz = fmaf(az, DT, vzz); szz = fmaf(vzz, DT, szz);
        float aw = fmaf(-ww, sww, fmaf(-d4.w, vww, fr.w)); vww = fmaf(aw, DT, vww); sww = fmaf(vww, DT, sww);
        float4 o;
        o.x = fminf(1.0f, fmaxf(-1.0f, sx + ox));
        o.y = fminf(1.0f, fmaxf(-1.0f, sy + oy));
        o.z = fminf(1.0f, fmaxf(-1.0f, szz + oz));
        o.w = fminf(1.0f, fmaxf(-1.0f, sww + ow));
        op[(size_t)k * (NSZ / 4)] = o;
    }
}

// ---------------------------------------------------------------------------
extern "C" void kernel_launch(void* const* d_in, const int* in_sizes, int n_in,
                              void* d_out, int out_size)
{
    const float* x     = (const float*)d_in[0];
    const float* W     = (const float*)d_in[1];
    const float* b     = (const float*)d_in[2];
    const float* amp   = (const float*)d_in[3];
    const float* freq  = (const float*)d_in[4];
    const float* phase = (const float*)d_in[5];
    const float* damp  = (const float*)d_in[6];
    float* out = (float*)d_out;
    (void)in_sizes; (void)n_in; (void)out_size;

    static bool attr_done = false;
    if (!attr_done) {
        cudaFuncSetAttribute(gemm_f16_kernel,
                             cudaFuncAttributeMaxDynamicSharedMemorySize, SMEM_BYTES);
        attr_done = true;
    }

    // 1. convert operands to fp16
    cvtA_kernel<<<(BSZ * DSZ / 4) / 256, 256>>>(x);
    cvtW_kernel<<<(NSZ * DSZ / 4) / 256, 256>>>(W);

    // 2. fp16 tensor-core GEMM -> g_force + fused per-chunk carries
    dim3 ggrid(NSZ / GBN, BSZ / GBM);
    gemm_f16_kernel<<<ggrid, 256, SMEM_BYTES>>>(b, freq, damp);

    // 3. combine carries, then final scan + oscillator + clip
    combine_kernel<<<NSZ / 256, 256>>>(freq, damp);
    dim3 sgrid(NSZ / 4 / 256, CCH);
    scanB_kernel<<<sgrid, 256>>>(freq, damp, amp, phase, out);
}

// round 12
// speedup vs baseline: 1.1829x; 1.1829x over previous
#include <cuda_runtime.h>
#include <cuda_fp16.h>
#include <math.h>
#include <stdint.h>

#define DT 0.01f
#define TWO_PI 6.28318530717958647692f

#define BSZ 4096
#define DSZ 2048
#define NSZ 4096

// scan chunking: 256 chunks of 16 rows; chunks grouped 16x16 for combine
#define CCH 256
#define LCH (BSZ / CCH)   // 16
#define NGRP 16
#define GSZ  16           // chunks per group

// GEMM tiling
#define GBM 128
#define GBN 128
#define GBK 32
#define ROWB 80
#define TILEB (128 * ROWB)
#define STAGEB (2 * TILEB)
#define NSTG 3
#define KITERS (DSZ / GBK)
#define PIPE_BYTES (NSTG * STAGEB)        // 61440
#define EPI_BYTES (128 * 129 * 4)         // 66048
#define SMEM_BYTES (EPI_BYTES > PIPE_BYTES ? EPI_BYTES : PIPE_BYTES)

// ---------------- static device scratch (no allocations allowed) -----------
__device__ __half g_Ah[(size_t)BSZ * DSZ];
__device__ __half g_Wh[(size_t)NSZ * DSZ];
__device__ float g_force[(size_t)BSZ * NSZ];
__device__ float g_cs[(size_t)CCH * NSZ], g_cv[(size_t)CCH * NSZ];   // chunk carries
__device__ float g_zs[(size_t)CCH * NSZ], g_zv[(size_t)CCH * NSZ];   // local offsets lz
__device__ float g_Cs[(size_t)NGRP * NSZ], g_Cv[(size_t)NGRP * NSZ]; // group carries
__device__ float g_GZs[(size_t)NGRP * NSZ], g_GZv[(size_t)NGRP * NSZ]; // group prefixes Z

// ---------------- helpers --------------------------------------------------
__device__ __forceinline__ uint32_t smem_u32(const void* p) {
    uint32_t a;
    asm("{ .reg .u64 t; cvta.to.shared.u64 t, %1; cvt.u32.u64 %0, t; }" : "=r"(a) : "l"(p));
    return a;
}
__device__ __forceinline__ void cp16(uint32_t dst, const void* src) {
    asm volatile("cp.async.cg.shared.global [%0], [%1], 16;\n" :: "r"(dst), "l"(src));
}
__device__ __forceinline__ void ldsm_x4(uint32_t* r, uint32_t addr) {
    asm volatile("ldmatrix.sync.aligned.m8n8.x4.shared.b16 {%0,%1,%2,%3}, [%4];"
                 : "=r"(r[0]), "=r"(r[1]), "=r"(r[2]), "=r"(r[3]) : "r"(addr));
}
__device__ __forceinline__ void mma_f16(float* d, const uint32_t* a, const uint32_t* b) {
    asm volatile(
        "mma.sync.aligned.m16n8k16.row.col.f32.f16.f16.f32 "
        "{%0,%1,%2,%3}, {%4,%5,%6,%7}, {%8,%9}, {%0,%1,%2,%3};"
        : "+f"(d[0]), "+f"(d[1]), "+f"(d[2]), "+f"(d[3])
        : "r"(a[0]), "r"(a[1]), "r"(a[2]), "r"(a[3]), "r"(b[0]), "r"(b[1]));
}
// one-step transition matrix, then 2^p squarings -> M^(2^p)
__device__ __forceinline__ void m_pow2(float w2, float dmp, int p,
                                       float& b00, float& b01, float& b10, float& b11) {
    b00 = 1.0f - w2 * DT * DT;
    b01 = DT * (1.0f - dmp * DT);
    b10 = -w2 * DT;
    b11 = 1.0f - dmp * DT;
    for (int q = 0; q < p; ++q) {
        float s00 = b00 * b00 + b01 * b10, s01 = b00 * b01 + b01 * b11;
        float s10 = b10 * b00 + b11 * b10, s11 = b10 * b01 + b11 * b11;
        b00 = s00; b01 = s01; b10 = s10; b11 = s11;
    }
}

// ---------------- convert kernels: fp32 -> fp16 ----------------------------
__global__ __launch_bounds__(256) void cvtA_kernel(const float* __restrict__ src) {
    size_t i = (size_t)blockIdx.x * 256 + threadIdx.x;
    float4 a = reinterpret_cast<const float4*>(src)[i];
    __half2 lo = __floats2half2_rn(a.x, a.y);
    __half2 hi = __floats2half2_rn(a.z, a.w);
    uint2 o;
    o.x = *reinterpret_cast<uint32_t*>(&lo);
    o.y = *reinterpret_cast<uint32_t*>(&hi);
    reinterpret_cast<uint2*>(g_Ah)[i] = o;
}
__global__ __launch_bounds__(256) void cvtW_kernel(const float* __restrict__ src) {
    size_t i = (size_t)blockIdx.x * 256 + threadIdx.x;
    float4 a = reinterpret_cast<const float4*>(src)[i];
    __half2 lo = __floats2half2_rn(a.x, a.y);
    __half2 hi = __floats2half2_rn(a.z, a.w);
    uint2 o;
    o.x = *reinterpret_cast<uint32_t*>(&lo);
    o.y = *reinterpret_cast<uint32_t*>(&hi);
    reinterpret_cast<uint2*>(g_Wh)[i] = o;
}

// ---------------- fp16 mma.sync GEMM + fused chunk-carry scan -------------
struct Frag {
    uint32_t a[4][4];
    uint32_t b[2][4];
};

__global__ __launch_bounds__(256, 1) void gemm_f16_kernel(
    const float* __restrict__ bias,
    const float* __restrict__ freq,
    const float* __restrict__ damp) {
    extern __shared__ char smem_raw[];
    const uint32_t sbase = smem_u32(smem_raw);
    const int tid = threadIdx.x;
    const int lane = tid & 31;
    const int wid = tid >> 5;
    const int m0 = blockIdx.y * GBM;
    const int n0 = blockIdx.x * GBN;
    const int wm = (wid >> 2) * 64;
    const int wn = (wid & 3) * 32;

    float acc[4][4][4];
    #pragma unroll
    for (int mt = 0; mt < 4; ++mt)
        #pragma unroll
        for (int nt = 0; nt < 4; ++nt)
            #pragma unroll
            for (int r = 0; r < 4; ++r)
                acc[mt][nt][r] = 0.0f;

    const uint32_t a_row_off = (uint32_t)(wm + (lane & 15)) * ROWB;
    const uint32_t a_csel = ((lane >> 4) & 1) * 16;
    const uint32_t b_row_off = (uint32_t)(wn + ((lane >> 4) & 1) * 8 + (lane & 7)) * ROWB;
    const uint32_t b_csel = ((lane >> 3) & 1) * 16;

    auto load_stage = [&](int s, int buf) {
        uint32_t sb = sbase + (uint32_t)buf * STAGEB;
        int k0 = s * GBK;
        #pragma unroll
        for (int it = 0; it < 2; ++it) {
            int c = tid + it * 256;
            int row = c >> 2, c16 = c & 3;
            uint32_t soff = (uint32_t)row * ROWB + (uint32_t)c16 * 16;
            size_t gA = (size_t)(m0 + row) * DSZ + k0 + c16 * 8;
            size_t gB = (size_t)(n0 + row) * DSZ + k0 + c16 * 8;
            cp16(sb + soff, g_Ah + gA);
            cp16(sb + TILEB + soff, g_Wh + gB);
        }
    };

    auto load_frags = [&](Frag& f, uint32_t sb, int ks) {
        const uint32_t acol = (uint32_t)(ks * 32) + a_csel;
        const uint32_t bcol = (uint32_t)(ks * 32) + b_csel;
        #pragma unroll
        for (int mt = 0; mt < 4; ++mt)
            ldsm_x4(f.a[mt], sb + a_row_off + (uint32_t)(mt * 16) * ROWB + acol);
        #pragma unroll
        for (int p = 0; p < 2; ++p)
            ldsm_x4(f.b[p], sb + TILEB + b_row_off + (uint32_t)(p * 16) * ROWB + bcol);
    };

    auto mma_all = [&](const Frag& f) {
        #pragma unroll
        for (int mt = 0; mt < 4; ++mt)
            #pragma unroll
            for (int p = 0; p < 2; ++p)
                #pragma unroll
                for (int h = 0; h < 2; ++h)
                    mma_f16(acc[mt][p * 2 + h], f.a[mt], &f.b[p][h * 2]);
    };

    load_stage(0, 0);
    asm volatile("cp.async.commit_group;\n" ::: "memory");
    load_stage(1, 1);
    asm volatile("cp.async.commit_group;\n" ::: "memory");
    asm volatile("cp.async.wait_group 1;\n" ::: "memory");
    __syncthreads();

    Frag fa, fb;
    load_frags(fa, sbase, 0);

    for (int s = 0; s < KITERS; ++s) {
        const uint32_t sb_cur = sbase + (uint32_t)(s % NSTG) * STAGEB;
        if (s + 2 < KITERS) {
            load_stage(s + 2, (s + 2) % NSTG);
            asm volatile("cp.async.commit_group;\n" ::: "memory");
        }
        load_frags(fb, sb_cur, 1);
        mma_all(fa);

        if (s + 1 < KITERS) {
            if (s + 2 < KITERS)
                asm volatile("cp.async.wait_group 1;\n" ::: "memory");
            else
                asm volatile("cp.async.wait_group 0;\n" ::: "memory");
            __syncthreads();
            load_frags(fa, sbase + (uint32_t)((s + 1) % NSTG) * STAGEB, 0);
        }
        mma_all(fb);
    }

    // ---- epilogue: bias, write force (gmem) + stage tile into smem -------
    __syncthreads();
    float* sf = reinterpret_cast<float*>(smem_raw);   // [col * 129 + row]

    #pragma unroll
    for (int nt = 0; nt < 4; ++nt) {
        int cl = wn + nt * 8 + (lane & 3) * 2;
        int c = n0 + cl;
        float b0 = __ldg(&bias[c]);
        float b1 = __ldg(&bias[c + 1]);
        #pragma unroll
        for (int mt = 0; mt < 4; ++mt) {
            int rl = wm + mt * 16 + (lane >> 2);
            int r = m0 + rl;
            float2 lo = make_float2(acc[mt][nt][0] + b0, acc[mt][nt][1] + b1);
            float2 hi = make_float2(acc[mt][nt][2] + b0, acc[mt][nt][3] + b1);
            *reinterpret_cast<float2*>(&g_force[(size_t)r * NSZ + c]) = lo;
            *reinterpret_cast<float2*>(&g_force[(size_t)(r + 8) * NSZ + c]) = hi;
            sf[cl * 129 + rl] = lo.x;
            sf[(cl + 1) * 129 + rl] = lo.y;
            sf[cl * 129 + rl + 8] = hi.x;
            sf[(cl + 1) * 129 + rl + 8] = hi.y;
        }
    }
    __syncthreads();

    // ---- fused scanA: per-(chunk, col) zero-init scan over 16 rows -------
    #pragma unroll
    for (int it = 0; it < 4; ++it) {
        int item = tid + it * 256;
        int cl = item & 127;
        int chunk = item >> 7;                        // 0..7
        int n = n0 + cl;
        float f = __ldg(&freq[n]);
        float dmp = __ldg(&damp[n]);
        float w2 = (TWO_PI * f) * (TWO_PI * f);
        const float* col = sf + cl * 129 + chunk * LCH;
        float s = 0.0f, v = 0.0f;
        #pragma unroll
        for (int k = 0; k < LCH; ++k) {
            float accel = fmaf(-w2, s, fmaf(-dmp, v, col[k]));
            v = fmaf(accel, DT, v);
            s = fmaf(v, DT, s);
        }
        int gchunk = blockIdx.y * 8 + chunk;
        g_cs[(size_t)gchunk * NSZ + n] = s;
        g_cv[(size_t)gchunk * NSZ + n] = v;
    }
}

// ---------------- combine L1: within-group local offsets + group carry ----
__global__ __launch_bounds__(256) void combine1_kernel(const float* __restrict__ freq,
                                                       const float* __restrict__ damp) {
    int idx = blockIdx.x * 256 + threadIdx.x;   // 0..NGRP*NSZ-1
    int n = idx & (NSZ - 1);
    int g = idx >> 12;                          // NSZ = 2^12
    float f = freq[n], dmp = damp[n];
    float w2 = (TWO_PI * f) * (TWO_PI * f);
    float e00, e01, e10, e11;
    m_pow2(w2, dmp, 4, e00, e01, e10, e11);     // E = M^16 = M^LCH

    float sz = 0.0f, vz = 0.0f;
    #pragma unroll
    for (int k = 0; k < GSZ; ++k) {
        size_t off = (size_t)(g * GSZ + k) * NSZ + n;
        g_zs[off] = sz;
        g_zv[off] = vz;
        float cs = g_cs[off], cv = g_cv[off];
        float ns = e00 * sz + e01 * vz + cs;
        float nv = e10 * sz + e11 * vz + cv;
        sz = ns; vz = nv;
    }
    g_Cs[(size_t)g * NSZ + n] = sz;
    g_Cv[(size_t)g * NSZ + n] = vz;
}

// ---------------- combine L2: scan over 16 group carries ------------------
__global__ __launch_bounds__(256) void combine2_kernel(const float* __restrict__ freq,
                                                       const float* __restrict__ damp) {
    int n = blockIdx.x * 256 + threadIdx.x;
    float f = freq[n], dmp = damp[n];
    float w2 = (TWO_PI * f) * (TWO_PI * f);
    float e00, e01, e10, e11;
    m_pow2(w2, dmp, 8, e00, e01, e10, e11);     // E_grp = M^256 = M^(LCH*GSZ)

    float sz = 0.0f, vz = 0.0f;
    #pragma unroll
    for (int g = 0; g < NGRP; ++g) {
        size_t off = (size_t)g * NSZ + n;
        g_GZs[off] = sz;
        g_GZv[off] = vz;
        float cs = g_Cs[off], cv = g_Cv[off];
        float ns = e00 * sz + e01 * vz + cs;
        float nv = e10 * sz + e11 * vz + cv;
        sz = ns; vz = nv;
    }
}

// ---------------- scan phase B: z = E^k Z_g + lz, scan, + osc, clip -------
__global__ __launch_bounds__(256) void scanB_kernel(const float* __restrict__ freq,
                                                    const float* __restrict__ damp,
                                                    const float* __restrict__ amp,
                                                    const float* __restrict__ phase,
                                                    float* __restrict__ out) {
    int c4 = blockIdx.x * 256 + threadIdx.x;
    int j = blockIdx.y;                    // chunk 0..255
    int g = j >> 4, kk = j & 15;
    int n = c4 * 4;
    float4 f4 = *reinterpret_cast<const float4*>(freq + n);
    float4 d4 = *reinterpret_cast<const float4*>(damp + n);
    float4 a4 = *reinterpret_cast<const float4*>(amp + n);
    float4 p4 = *reinterpret_cast<const float4*>(phase + n);

    float w2[4] = {(TWO_PI * f4.x) * (TWO_PI * f4.x), (TWO_PI * f4.y) * (TWO_PI * f4.y),
                   (TWO_PI * f4.z) * (TWO_PI * f4.z), (TWO_PI * f4.w) * (TWO_PI * f4.w)};
    float dm[4] = {d4.x, d4.y, d4.z, d4.w};
    float osc[4];
    osc[0] = a4.x * sinf(fmaf(TWO_PI * f4.x, DT, p4.x));
    osc[1] = a4.y * sinf(fmaf(TWO_PI * f4.y, DT, p4.y));
    osc[2] = a4.z * sinf(fmaf(TWO_PI * f4.z, DT, p4.z));
    osc[3] = a4.w * sinf(fmaf(TWO_PI * f4.w, DT, p4.w));

    float4 lzs = *reinterpret_cast<const float4*>(g_zs + (size_t)j * NSZ + n);
    float4 lzv = *reinterpret_cast<const float4*>(g_zv + (size_t)j * NSZ + n);
    float4 Zs4 = *reinterpret_cast<const float4*>(g_GZs + (size_t)g * NSZ + n);
    float4 Zv4 = *reinterpret_cast<const float4*>(g_GZv + (size_t)g * NSZ + n);
    float lzsa[4] = {lzs.x, lzs.y, lzs.z, lzs.w};
    float lzva[4] = {lzv.x, lzv.y, lzv.z, lzv.w};
    float Zsa[4] = {Zs4.x, Zs4.y, Zs4.z, Zs4.w};
    float Zva[4] = {Zv4.x, Zv4.y, Zv4.z, Zv4.w};

    float s[4], v[4];
    #pragma unroll
    for (int l = 0; l < 4; ++l) {
        float e00, e01, e10, e11;
        m_pow2(w2[l], dm[l], 4, e00, e01, e10, e11);   // E = M^16
        float us = Zsa[l], uv = Zva[l];
        for (int t = 0; t < kk; ++t) {                 // u = E^kk Z
            float ns = e00 * us + e01 * uv;
            float nv = e10 * us + e11 * uv;
            us = ns; uv = nv;
        }
        s[l] = lzsa[l] + us;
        v[l] = lzva[l] + uv;
    }

    const float4* fp = reinterpret_cast<const float4*>(g_force + (size_t)j * LCH * NSZ + n);
    float4* op = reinterpret_cast<float4*>(out + (size_t)j * LCH * NSZ + n);
    #pragma unroll
    for (int k = 0; k < LCH; ++k) {
        float4 fr = fp[(size_t)k * (NSZ / 4)];
        float fra[4] = {fr.x, fr.y, fr.z, fr.w};
        float o[4];
        #pragma unroll
        for (int l = 0; l < 4; ++l) {
            float accel = fmaf(-w2[l], s[l], fmaf(-dm[l], v[l], fra[l]));
            v[l] = fmaf(accel, DT, v[l]);
            s[l] = fmaf(v[l], DT, s[l]);
            o[l] = fminf(1.0f, fmaxf(-1.0f, s[l] + osc[l]));
        }
        op[(size_t)k * (NSZ / 4)] = make_float4(o[0], o[1], o[2], o[3]);
    }
}

// ---------------------------------------------------------------------------
extern "C" void kernel_launch(void* const* d_in, const int* in_sizes, int n_in,
                              void* d_out, int out_size)
{
    const float* x     = (const float*)d_in[0];
    const float* W     = (const float*)d_in[1];
    const float* b     = (const float*)d_in[2];
    const float* amp   = (const float*)d_in[3];
    const float* freq  = (const float*)d_in[4];
    const float* phase = (const float*)d_in[5];
    const float* damp  = (const float*)d_in[6];
    float* out = (float*)d_out;
    (void)in_sizes; (void)n_in; (void)out_size;

    static bool attr_done = false;
    if (!attr_done) {
        cudaFuncSetAttribute(gemm_f16_kernel,
                             cudaFuncAttributeMaxDynamicSharedMemorySize, SMEM_BYTES);
        attr_done = true;
    }

    // 1. convert operands to fp16
    cvtA_kernel<<<(BSZ * DSZ / 4) / 256, 256>>>(x);
    cvtW_kernel<<<(NSZ * DSZ / 4) / 256, 256>>>(W);

    // 2. fp16 tensor-core GEMM -> g_force + fused per-chunk carries
    dim3 ggrid(NSZ / GBN, BSZ / GBM);
    gemm_f16_kernel<<<ggrid, 256, SMEM_BYTES>>>(b, freq, damp);

    // 3. hierarchical combine (no serial chain longer than 16)
    combine1_kernel<<<NGRP * NSZ / 256, 256>>>(freq, damp);
    combine2_kernel<<<NSZ / 256, 256>>>(freq, damp);

    // 4. final scan + oscillator + clip
    dim3 sgrid(NSZ / 4 / 256, CCH);
    scanB_kernel<<<sgrid, 256>>>(freq, damp, amp, phase, out);
}

// round 14
// speedup vs baseline: 1.2722x; 1.0755x over previous
#include <cuda_runtime.h>
#include <cuda_fp16.h>
#include <math.h>
#include <stdint.h>

#define DT 0.01f
#define TWO_PI 6.28318530717958647692f

#define BSZ 4096
#define DSZ 2048
#define NSZ 4096

// scan chunking: 256 chunks of 16 rows; chunks grouped 16x16 for combine
#define CCH 256
#define LCH (BSZ / CCH)   // 16
#define NGRP 16
#define GSZ  16

// GEMM tiling
#define GBM 128
#define GBN 128
#define GBK 32
#define ROWB 80
#define TILEB (128 * ROWB)
#define STAGEB (2 * TILEB)
#define NSTG 3
#define KITERS (DSZ / GBK)
#define PIPE_BYTES (NSTG * STAGEB)        // 61440
#define EPI_BYTES (128 * 129 * 4)         // 66048
#define SMEM_BYTES (EPI_BYTES > PIPE_BYTES ? EPI_BYTES : PIPE_BYTES)

// ---------------- static device scratch (no allocations allowed) -----------
__device__ __half g_Ah[(size_t)BSZ * DSZ];
__device__ __half g_Wh[(size_t)NSZ * DSZ];
__device__ __half g_state[(size_t)BSZ * NSZ];                        // fp16 local states
__device__ float g_cs[(size_t)CCH * NSZ], g_cv[(size_t)CCH * NSZ];   // chunk carries
__device__ float g_zs[(size_t)CCH * NSZ], g_zv[(size_t)CCH * NSZ];   // local offsets lz
__device__ float g_Cs[(size_t)NGRP * NSZ], g_Cv[(size_t)NGRP * NSZ]; // group carries
__device__ float g_GZs[(size_t)NGRP * NSZ], g_GZv[(size_t)NGRP * NSZ]; // group prefixes

// ---------------- helpers --------------------------------------------------
__device__ __forceinline__ uint32_t smem_u32(const void* p) {
    uint32_t a;
    asm("{ .reg .u64 t; cvta.to.shared.u64 t, %1; cvt.u32.u64 %0, t; }" : "=r"(a) : "l"(p));
    return a;
}
__device__ __forceinline__ void cp16(uint32_t dst, const void* src) {
    asm volatile("cp.async.cg.shared.global [%0], [%1], 16;\n" :: "r"(dst), "l"(src));
}
__device__ __forceinline__ void ldsm_x4(uint32_t* r, uint32_t addr) {
    asm volatile("ldmatrix.sync.aligned.m8n8.x4.shared.b16 {%0,%1,%2,%3}, [%4];"
                 : "=r"(r[0]), "=r"(r[1]), "=r"(r[2]), "=r"(r[3]) : "r"(addr));
}
__device__ __forceinline__ void mma_f16(float* d, const uint32_t* a, const uint32_t* b) {
    asm volatile(
        "mma.sync.aligned.m16n8k16.row.col.f32.f16.f16.f32 "
        "{%0,%1,%2,%3}, {%4,%5,%6,%7}, {%8,%9}, {%0,%1,%2,%3};"
        : "+f"(d[0]), "+f"(d[1]), "+f"(d[2]), "+f"(d[3])
        : "r"(a[0]), "r"(a[1]), "r"(a[2]), "r"(a[3]), "r"(b[0]), "r"(b[1]));
}
// one-step transition matrix, then p squarings -> M^(2^p)
__device__ __forceinline__ void m_pow2(float w2, float dmp, int p,
                                       float& b00, float& b01, float& b10, float& b11) {
    b00 = 1.0f - w2 * DT * DT;
    b01 = DT * (1.0f - dmp * DT);
    b10 = -w2 * DT;
    b11 = 1.0f - dmp * DT;
    for (int q = 0; q < p; ++q) {
        float s00 = b00 * b00 + b01 * b10, s01 = b00 * b01 + b01 * b11;
        float s10 = b10 * b00 + b11 * b10, s11 = b10 * b01 + b11 * b11;
        b00 = s00; b01 = s01; b10 = s10; b11 = s11;
    }
}

// ---------------- convert kernels: fp32 -> fp16 ----------------------------
__global__ __launch_bounds__(256) void cvtA_kernel(const float* __restrict__ src) {
    size_t i = (size_t)blockIdx.x * 256 + threadIdx.x;
    float4 a = reinterpret_cast<const float4*>(src)[i];
    __half2 lo = __floats2half2_rn(a.x, a.y);
    __half2 hi = __floats2half2_rn(a.z, a.w);
    uint2 o;
    o.x = *reinterpret_cast<uint32_t*>(&lo);
    o.y = *reinterpret_cast<uint32_t*>(&hi);
    reinterpret_cast<uint2*>(g_Ah)[i] = o;
}
__global__ __launch_bounds__(256) void cvtW_kernel(const float* __restrict__ src) {
    size_t i = (size_t)blockIdx.x * 256 + threadIdx.x;
    float4 a = reinterpret_cast<const float4*>(src)[i];
    __half2 lo = __floats2half2_rn(a.x, a.y);
    __half2 hi = __floats2half2_rn(a.z, a.w);
    uint2 o;
    o.x = *reinterpret_cast<uint32_t*>(&lo);
    o.y = *reinterpret_cast<uint32_t*>(&hi);
    reinterpret_cast<uint2*>(g_Wh)[i] = o;
}

// ---------------- fp16 mma.sync GEMM + fused local scan -------------------
struct Frag {
    uint32_t a[4][4];
    uint32_t b[2][4];
};

__global__ __launch_bounds__(256, 1) void gemm_f16_kernel(
    const float* __restrict__ bias,
    const float* __restrict__ freq,
    const float* __restrict__ damp) {
    extern __shared__ char smem_raw[];
    const uint32_t sbase = smem_u32(smem_raw);
    const int tid = threadIdx.x;
    const int lane = tid & 31;
    const int wid = tid >> 5;
    const int m0 = blockIdx.y * GBM;
    const int n0 = blockIdx.x * GBN;
    const int wm = (wid >> 2) * 64;
    const int wn = (wid & 3) * 32;

    float acc[4][4][4];
    #pragma unroll
    for (int mt = 0; mt < 4; ++mt)
        #pragma unroll
        for (int nt = 0; nt < 4; ++nt)
            #pragma unroll
            for (int r = 0; r < 4; ++r)
                acc[mt][nt][r] = 0.0f;

    const uint32_t a_row_off = (uint32_t)(wm + (lane & 15)) * ROWB;
    const uint32_t a_csel = ((lane >> 4) & 1) * 16;
    const uint32_t b_row_off = (uint32_t)(wn + ((lane >> 4) & 1) * 8 + (lane & 7)) * ROWB;
    const uint32_t b_csel = ((lane >> 3) & 1) * 16;

    auto load_stage = [&](int s, int buf) {
        uint32_t sb = sbase + (uint32_t)buf * STAGEB;
        int k0 = s * GBK;
        #pragma unroll
        for (int it = 0; it < 2; ++it) {
            int c = tid + it * 256;
            int row = c >> 2, c16 = c & 3;
            uint32_t soff = (uint32_t)row * ROWB + (uint32_t)c16 * 16;
            size_t gA = (size_t)(m0 + row) * DSZ + k0 + c16 * 8;
            size_t gB = (size_t)(n0 + row) * DSZ + k0 + c16 * 8;
            cp16(sb + soff, g_Ah + gA);
            cp16(sb + TILEB + soff, g_Wh + gB);
        }
    };

    auto load_frags = [&](Frag& f, uint32_t sb, int ks) {
        const uint32_t acol = (uint32_t)(ks * 32) + a_csel;
        const uint32_t bcol = (uint32_t)(ks * 32) + b_csel;
        #pragma unroll
        for (int mt = 0; mt < 4; ++mt)
            ldsm_x4(f.a[mt], sb + a_row_off + (uint32_t)(mt * 16) * ROWB + acol);
        #pragma unroll
        for (int p = 0; p < 2; ++p)
            ldsm_x4(f.b[p], sb + TILEB + b_row_off + (uint32_t)(p * 16) * ROWB + bcol);
    };

    auto mma_all = [&](const Frag& f) {
        #pragma unroll
        for (int mt = 0; mt < 4; ++mt)
            #pragma unroll
            for (int p = 0; p < 2; ++p)
                #pragma unroll
                for (int h = 0; h < 2; ++h)
                    mma_f16(acc[mt][p * 2 + h], f.a[mt], &f.b[p][h * 2]);
    };

    load_stage(0, 0);
    asm volatile("cp.async.commit_group;\n" ::: "memory");
    load_stage(1, 1);
    asm volatile("cp.async.commit_group;\n" ::: "memory");
    asm volatile("cp.async.wait_group 1;\n" ::: "memory");
    __syncthreads();

    Frag fa, fb;
    load_frags(fa, sbase, 0);

    for (int s = 0; s < KITERS; ++s) {
        const uint32_t sb_cur = sbase + (uint32_t)(s % NSTG) * STAGEB;
        if (s + 2 < KITERS) {
            load_stage(s + 2, (s + 2) % NSTG);
            asm volatile("cp.async.commit_group;\n" ::: "memory");
        }
        load_frags(fb, sb_cur, 1);
        mma_all(fa);

        if (s + 1 < KITERS) {
            if (s + 2 < KITERS)
                asm volatile("cp.async.wait_group 1;\n" ::: "memory");
            else
                asm volatile("cp.async.wait_group 0;\n" ::: "memory");
            __syncthreads();
            load_frags(fa, sbase + (uint32_t)((s + 1) % NSTG) * STAGEB, 0);
        }
        mma_all(fb);
    }

    // ---- epilogue: bias, stage tile into smem (no fp32 force to gmem) ----
    __syncthreads();
    float* sf = reinterpret_cast<float*>(smem_raw);   // [col * 129 + row]

    #pragma unroll
    for (int nt = 0; nt < 4; ++nt) {
        int cl = wn + nt * 8 + (lane & 3) * 2;
        int c = n0 + cl;
        float b0 = __ldg(&bias[c]);
        float b1 = __ldg(&bias[c + 1]);
        #pragma unroll
        for (int mt = 0; mt < 4; ++mt) {
            int rl = wm + mt * 16 + (lane >> 2);
            sf[cl * 129 + rl] = acc[mt][nt][0] + b0;
            sf[(cl + 1) * 129 + rl] = acc[mt][nt][1] + b1;
            sf[cl * 129 + rl + 8] = acc[mt][nt][2] + b0;
            sf[(cl + 1) * 129 + rl + 8] = acc[mt][nt][3] + b1;
        }
    }
    __syncthreads();

    // ---- fused local scan: per-(chunk, col); write fp16 states + carries -
    #pragma unroll
    for (int it = 0; it < 4; ++it) {
        int item = tid + it * 256;
        int cl = item & 127;
        int chunk = item >> 7;                        // 0..7
        int n = n0 + cl;
        float f = __ldg(&freq[n]);
        float dmp = __ldg(&damp[n]);
        float w2 = (TWO_PI * f) * (TWO_PI * f);
        const float* col = sf + cl * 129 + chunk * LCH;
        int gchunk = blockIdx.y * 8 + chunk;
        __half* st = g_state + (size_t)gchunk * LCH * NSZ + n;
        float s = 0.0f, v = 0.0f;
        #pragma unroll
        for (int k = 0; k < LCH; ++k) {
            float accel = fmaf(-w2, s, fmaf(-dmp, v, col[k]));
            v = fmaf(accel, DT, v);
            s = fmaf(v, DT, s);
            st[(size_t)k * NSZ] = __float2half_rn(s);
        }
        g_cs[(size_t)gchunk * NSZ + n] = s;
        g_cv[(size_t)gchunk * NSZ + n] = v;
    }
}

// ---------------- combine L1: within-group local offsets + group carry ----
__global__ __launch_bounds__(256) void combine1_kernel(const float* __restrict__ freq,
                                                       const float* __restrict__ damp) {
    int idx = blockIdx.x * 256 + threadIdx.x;
    int n = idx & (NSZ - 1);
    int g = idx >> 12;
    float f = freq[n], dmp = damp[n];
    float w2 = (TWO_PI * f) * (TWO_PI * f);
    float e00, e01, e10, e11;
    m_pow2(w2, dmp, 4, e00, e01, e10, e11);     // E = M^16

    float sz = 0.0f, vz = 0.0f;
    #pragma unroll
    for (int k = 0; k < GSZ; ++k) {
        size_t off = (size_t)(g * GSZ + k) * NSZ + n;
        g_zs[off] = sz;
        g_zv[off] = vz;
        float cs = g_cs[off], cv = g_cv[off];
        float ns = e00 * sz + e01 * vz + cs;
        float nv = e10 * sz + e11 * vz + cv;
        sz = ns; vz = nv;
    }
    g_Cs[(size_t)g * NSZ + n] = sz;
    g_Cv[(size_t)g * NSZ + n] = vz;
}

// ---------------- combine L2: scan over 16 group carries ------------------
__global__ __launch_bounds__(256) void combine2_kernel(const float* __restrict__ freq,
                                                       const float* __restrict__ damp) {
    int n = blockIdx.x * 256 + threadIdx.x;
    float f = freq[n], dmp = damp[n];
    float w2 = (TWO_PI * f) * (TWO_PI * f);
    float e00, e01, e10, e11;
    m_pow2(w2, dmp, 8, e00, e01, e10, e11);     // E_grp = M^256

    float sz = 0.0f, vz = 0.0f;
    #pragma unroll
    for (int g = 0; g < NGRP; ++g) {
        size_t off = (size_t)g * NSZ + n;
        g_GZs[off] = sz;
        g_GZv[off] = vz;
        float cs = g_Cs[off], cv = g_Cv[off];
        float ns = e00 * sz + e01 * vz + cs;
        float nv = e10 * sz + e11 * vz + cv;
        sz = ns; vz = nv;
    }
}

// ---------------- fixup: out = clip(local + hom(z) + osc) -----------------
// Homogeneous chain is register-only; loads (fp16 local states) just add.
__global__ __launch_bounds__(256) void fixup_kernel(const float* __restrict__ freq,
                                                    const float* __restrict__ damp,
                                                    const float* __restrict__ amp,
                                                    const float* __restrict__ phase,
                                                    float* __restrict__ out) {
    int c4 = blockIdx.x * 256 + threadIdx.x;   // 0..NSZ/4-1
    int j = blockIdx.y;                        // chunk 0..255
    int g = j >> 4, kk = j & 15;
    int n = c4 * 4;
    float4 f4 = *reinterpret_cast<const float4*>(freq + n);
    float4 d4 = *reinterpret_cast<const float4*>(damp + n);
    float4 a4 = *reinterpret_cast<const float4*>(amp + n);
    float4 p4 = *reinterpret_cast<const float4*>(phase + n);

    float w2[4] = {(TWO_PI * f4.x) * (TWO_PI * f4.x), (TWO_PI * f4.y) * (TWO_PI * f4.y),
                   (TWO_PI * f4.z) * (TWO_PI * f4.z), (TWO_PI * f4.w) * (TWO_PI * f4.w)};
    float dm[4] = {d4.x, d4.y, d4.z, d4.w};
    float osc[4];
    osc[0] = a4.x * sinf(fmaf(TWO_PI * f4.x, DT, p4.x));
    osc[1] = a4.y * sinf(fmaf(TWO_PI * f4.y, DT, p4.y));
    osc[2] = a4.z * sinf(fmaf(TWO_PI * f4.z, DT, p4.z));
    osc[3] = a4.w * sinf(fmaf(TWO_PI * f4.w, DT, p4.w));

    float4 lzs = *reinterpret_cast<const float4*>(g_zs + (size_t)j * NSZ + n);
    float4 lzv = *reinterpret_cast<const float4*>(g_zv + (size_t)j * NSZ + n);
    float4 Zs4 = *reinterpret_cast<const float4*>(g_GZs + (size_t)g * NSZ + n);
    float4 Zv4 = *reinterpret_cast<const float4*>(g_GZv + (size_t)g * NSZ + n);
    float lzsa[4] = {lzs.x, lzs.y, lzs.z, lzs.w};
    float lzva[4] = {lzv.x, lzv.y, lzv.z, lzv.w};
    float Zsa[4] = {Zs4.x, Zs4.y, Zs4.z, Zs4.w};
    float Zva[4] = {Zv4.x, Zv4.y, Zv4.z, Zv4.w};

    // z_j = E^kk Z_g + lz (state/vel entering this chunk)
    float s[4], v[4];
    #pragma unroll
    for (int l = 0; l < 4; ++l) {
        float e00, e01, e10, e11;
        m_pow2(w2[l], dm[l], 4, e00, e01, e10, e11);   // E = M^16
        float us = Zsa[l], uv = Zva[l];
        for (int t = 0; t < kk; ++t) {
            float ns = e00 * us + e01 * uv;
            float nv = e10 * us + e11 * uv;
            us = ns; uv = nv;
        }
        s[l] = lzsa[l] + us;
        v[l] = lzva[l] + uv;
    }

    // row stride in uint2 units: NSZ halves = NSZ/4 uint2 (4 halves per uint2)
    const uint2* sp = reinterpret_cast<const uint2*>(g_state + (size_t)j * LCH * NSZ + n);
    float4* op = reinterpret_cast<float4*>(out + (size_t)j * LCH * NSZ + n);
    #pragma unroll
    for (int k = 0; k < LCH; ++k) {
        uint2 lraw = sp[(size_t)k * (NSZ / 4)];
        __half2 h0 = *reinterpret_cast<__half2*>(&lraw.x);
        __half2 h1 = *reinterpret_cast<__half2*>(&lraw.y);
        float la[4] = {__low2float(h0), __high2float(h0), __low2float(h1), __high2float(h1)};
        float o[4];
        #pragma unroll
        for (int l = 0; l < 4; ++l) {
            float accel = fmaf(-w2[l], s[l], -dm[l] * v[l]);   // homogeneous step
            v[l] = fmaf(accel, DT, v[l]);
            s[l] = fmaf(v[l], DT, s[l]);
            o[l] = fminf(1.0f, fmaxf(-1.0f, la[l] + s[l] + osc[l]));
        }
        op[(size_t)k * (NSZ / 4)] = make_float4(o[0], o[1], o[2], o[3]);
    }
}

// ---------------------------------------------------------------------------
extern "C" void kernel_launch(void* const* d_in, const int* in_sizes, int n_in,
                              void* d_out, int out_size)
{
    const float* x     = (const float*)d_in[0];
    const float* W     = (const float*)d_in[1];
    const float* b     = (const float*)d_in[2];
    const float* amp   = (const float*)d_in[3];
    const float* freq  = (const float*)d_in[4];
    const float* phase = (const float*)d_in[5];
    const float* damp  = (const float*)d_in[6];
    float* out = (float*)d_out;
    (void)in_sizes; (void)n_in; (void)out_size;

    static bool attr_done = false;
    if (!attr_done) {
        cudaFuncSetAttribute(gemm_f16_kernel,
                             cudaFuncAttributeMaxDynamicSharedMemorySize, SMEM_BYTES);
        attr_done = true;
    }

    // 1. convert operands to fp16
    cvtA_kernel<<<(BSZ * DSZ / 4) / 256, 256>>>(x);
    cvtW_kernel<<<(NSZ * DSZ / 4) / 256, 256>>>(W);

    // 2. fp16 GEMM -> fp16 local states + fp32 chunk carries (fused scan)
    dim3 ggrid(NSZ / GBN, BSZ / GBM);
    gemm_f16_kernel<<<ggrid, 256, SMEM_BYTES>>>(b, freq, damp);

    // 3. hierarchical combine (no serial chain longer than 16)
    combine1_kernel<<<NGRP * NSZ / 256, 256>>>(freq, damp);
    combine2_kernel<<<NSZ / 256, 256>>>(freq, damp);

    // 4. fixup: add homogeneous correction + oscillator, clip, write out
    dim3 sgrid(NSZ / 4 / 256, CCH);
    fixup_kernel<<<sgrid, 256>>>(freq, damp, amp, phase, out);
}

// round 15
// speedup vs baseline: 1.4012x; 1.1014x over previous
#include <cuda_runtime.h>
#include <cuda_fp16.h>
#include <math.h>
#include <stdint.h>

#define DT 0.01f
#define TWO_PI 6.28318530717958647692f

#define BSZ 4096
#define DSZ 2048
#define NSZ 4096

// scan chunking: 256 chunks of 16 rows; chunks grouped 16x16 for combine
#define CCH 256
#define LCH (BSZ / CCH)   // 16
#define NGRP 16
#define GSZ  16

// GEMM tiling
#define GBM 128
#define GBN 128
#define GBK 32
#define ROWB 80
#define TILEB (128 * ROWB)
#define STAGEB (2 * TILEB)
#define NSTG 3
#define KITERS (DSZ / GBK)
#define PIPE_BYTES (NSTG * STAGEB)        // 61440
#define EPI_BYTES (128 * 129 * 4)         // 66048
#define SMEM_BYTES (EPI_BYTES > PIPE_BYTES ? EPI_BYTES : PIPE_BYTES)

// ---------------- static device scratch (no allocations allowed) -----------
__device__ __half g_Ah[(size_t)BSZ * DSZ];
__device__ __half g_Wh[(size_t)NSZ * DSZ];
__device__ __half g_state[(size_t)BSZ * NSZ];                        // fp16 local states
__device__ float g_cs[(size_t)CCH * NSZ], g_cv[(size_t)CCH * NSZ];   // chunk carries
__device__ float g_zs[(size_t)CCH * NSZ], g_zv[(size_t)CCH * NSZ];   // local offsets lz
__device__ float g_Cs[(size_t)NGRP * NSZ], g_Cv[(size_t)NGRP * NSZ]; // group carries
__device__ float g_GZs[(size_t)NGRP * NSZ], g_GZv[(size_t)NGRP * NSZ]; // group prefixes

// ---------------- helpers --------------------------------------------------
__device__ __forceinline__ uint32_t smem_u32(const void* p) {
    uint32_t a;
    asm("{ .reg .u64 t; cvta.to.shared.u64 t, %1; cvt.u32.u64 %0, t; }" : "=r"(a) : "l"(p));
    return a;
}
__device__ __forceinline__ void cp16(uint32_t dst, const void* src) {
    asm volatile("cp.async.cg.shared.global [%0], [%1], 16;\n" :: "r"(dst), "l"(src));
}
__device__ __forceinline__ void ldsm_x4(uint32_t* r, uint32_t addr) {
    asm volatile("ldmatrix.sync.aligned.m8n8.x4.shared.b16 {%0,%1,%2,%3}, [%4];"
                 : "=r"(r[0]), "=r"(r[1]), "=r"(r[2]), "=r"(r[3]) : "r"(addr));
}
__device__ __forceinline__ void mma_f16(float* d, const uint32_t* a, const uint32_t* b) {
    asm volatile(
        "mma.sync.aligned.m16n8k16.row.col.f32.f16.f16.f32 "
        "{%0,%1,%2,%3}, {%4,%5,%6,%7}, {%8,%9}, {%0,%1,%2,%3};"
        : "+f"(d[0]), "+f"(d[1]), "+f"(d[2]), "+f"(d[3])
        : "r"(a[0]), "r"(a[1]), "r"(a[2]), "r"(a[3]), "r"(b[0]), "r"(b[1]));
}
// one-step transition matrix, then p squarings -> M^(2^p)
__device__ __forceinline__ void m_pow2(float w2, float dmp, int p,
                                       float& b00, float& b01, float& b10, float& b11) {
    b00 = 1.0f - w2 * DT * DT;
    b01 = DT * (1.0f - dmp * DT);
    b10 = -w2 * DT;
    b11 = 1.0f - dmp * DT;
    for (int q = 0; q < p; ++q) {
        float s00 = b00 * b00 + b01 * b10, s01 = b00 * b01 + b01 * b11;
        float s10 = b10 * b00 + b11 * b10, s11 = b10 * b01 + b11 * b11;
        b00 = s00; b01 = s01; b10 = s10; b11 = s11;
    }
}

// ---------------- merged convert kernel: fp32 -> fp16, 8 elems/thread -----
__global__ __launch_bounds__(256) void cvt_kernel(const float* __restrict__ x,
                                                  const float* __restrict__ W) {
    const size_t NA8 = (size_t)BSZ * DSZ / 8;     // uint4-out count for A
    size_t i = (size_t)blockIdx.x * 256 + threadIdx.x;
    const float4* src;
    uint4* dst;
    size_t j;
    if (i < NA8) {
        src = reinterpret_cast<const float4*>(x);
        dst = reinterpret_cast<uint4*>(g_Ah);
        j = i;
    } else {
        src = reinterpret_cast<const float4*>(W);
        dst = reinterpret_cast<uint4*>(g_Wh);
        j = i - NA8;
    }
    float4 a0 = src[2 * j];
    float4 a1 = src[2 * j + 1];
    __half2 h0 = __floats2half2_rn(a0.x, a0.y);
    __half2 h1 = __floats2half2_rn(a0.z, a0.w);
    __half2 h2 = __floats2half2_rn(a1.x, a1.y);
    __half2 h3 = __floats2half2_rn(a1.z, a1.w);
    uint4 o;
    o.x = *reinterpret_cast<uint32_t*>(&h0);
    o.y = *reinterpret_cast<uint32_t*>(&h1);
    o.z = *reinterpret_cast<uint32_t*>(&h2);
    o.w = *reinterpret_cast<uint32_t*>(&h3);
    dst[j] = o;
}

// ---------------- fp16 mma.sync GEMM + fused local scan -------------------
struct Frag {
    uint32_t a[4][4];
    uint32_t b[2][4];
};

__global__ __launch_bounds__(256, 1) void gemm_f16_kernel(
    const float* __restrict__ bias,
    const float* __restrict__ freq,
    const float* __restrict__ damp) {
    extern __shared__ char smem_raw[];
    const uint32_t sbase = smem_u32(smem_raw);
    const int tid = threadIdx.x;
    const int lane = tid & 31;
    const int wid = tid >> 5;
    const int m0 = blockIdx.y * GBM;
    const int n0 = blockIdx.x * GBN;
    const int wm = (wid >> 2) * 64;
    const int wn = (wid & 3) * 32;

    float acc[4][4][4];
    #pragma unroll
    for (int mt = 0; mt < 4; ++mt)
        #pragma unroll
        for (int nt = 0; nt < 4; ++nt)
            #pragma unroll
            for (int r = 0; r < 4; ++r)
                acc[mt][nt][r] = 0.0f;

    const uint32_t a_row_off = (uint32_t)(wm + (lane & 15)) * ROWB;
    const uint32_t a_csel = ((lane >> 4) & 1) * 16;
    const uint32_t b_row_off = (uint32_t)(wn + ((lane >> 4) & 1) * 8 + (lane & 7)) * ROWB;
    const uint32_t b_csel = ((lane >> 3) & 1) * 16;

    auto load_stage = [&](int s, int buf) {
        uint32_t sb = sbase + (uint32_t)buf * STAGEB;
        int k0 = s * GBK;
        #pragma unroll
        for (int it = 0; it < 2; ++it) {
            int c = tid + it * 256;
            int row = c >> 2, c16 = c & 3;
            uint32_t soff = (uint32_t)row * ROWB + (uint32_t)c16 * 16;
            size_t gA = (size_t)(m0 + row) * DSZ + k0 + c16 * 8;
            size_t gB = (size_t)(n0 + row) * DSZ + k0 + c16 * 8;
            cp16(sb + soff, g_Ah + gA);
            cp16(sb + TILEB + soff, g_Wh + gB);
        }
    };

    auto load_frags = [&](Frag& f, uint32_t sb, int ks) {
        const uint32_t acol = (uint32_t)(ks * 32) + a_csel;
        const uint32_t bcol = (uint32_t)(ks * 32) + b_csel;
        #pragma unroll
        for (int mt = 0; mt < 4; ++mt)
            ldsm_x4(f.a[mt], sb + a_row_off + (uint32_t)(mt * 16) * ROWB + acol);
        #pragma unroll
        for (int p = 0; p < 2; ++p)
            ldsm_x4(f.b[p], sb + TILEB + b_row_off + (uint32_t)(p * 16) * ROWB + bcol);
    };

    auto mma_all = [&](const Frag& f) {
        #pragma unroll
        for (int mt = 0; mt < 4; ++mt)
            #pragma unroll
            for (int p = 0; p < 2; ++p)
                #pragma unroll
                for (int h = 0; h < 2; ++h)
                    mma_f16(acc[mt][p * 2 + h], f.a[mt], &f.b[p][h * 2]);
    };

    load_stage(0, 0);
    asm volatile("cp.async.commit_group;\n" ::: "memory");
    load_stage(1, 1);
    asm volatile("cp.async.commit_group;\n" ::: "memory");
    asm volatile("cp.async.wait_group 1;\n" ::: "memory");
    __syncthreads();

    Frag fa, fb;
    load_frags(fa, sbase, 0);

    for (int s = 0; s < KITERS; ++s) {
        const uint32_t sb_cur = sbase + (uint32_t)(s % NSTG) * STAGEB;
        if (s + 2 < KITERS) {
            load_stage(s + 2, (s + 2) % NSTG);
            asm volatile("cp.async.commit_group;\n" ::: "memory");
        }
        load_frags(fb, sb_cur, 1);
        mma_all(fa);

        if (s + 1 < KITERS) {
            if (s + 2 < KITERS)
                asm volatile("cp.async.wait_group 1;\n" ::: "memory");
            else
                asm volatile("cp.async.wait_group 0;\n" ::: "memory");
            __syncthreads();
            load_frags(fa, sbase + (uint32_t)((s + 1) % NSTG) * STAGEB, 0);
        }
        mma_all(fb);
    }

    // ---- epilogue: bias, stage tile into smem ----------------------------
    __syncthreads();
    float* sf = reinterpret_cast<float*>(smem_raw);   // [col * 129 + row]

    #pragma unroll
    for (int nt = 0; nt < 4; ++nt) {
        int cl = wn + nt * 8 + (lane & 3) * 2;
        int c = n0 + cl;
        float b0 = __ldg(&bias[c]);
        float b1 = __ldg(&bias[c + 1]);
        #pragma unroll
        for (int mt = 0; mt < 4; ++mt) {
            int rl = wm + mt * 16 + (lane >> 2);
            sf[cl * 129 + rl] = acc[mt][nt][0] + b0;
            sf[(cl + 1) * 129 + rl] = acc[mt][nt][1] + b1;
            sf[cl * 129 + rl + 8] = acc[mt][nt][2] + b0;
            sf[(cl + 1) * 129 + rl + 8] = acc[mt][nt][3] + b1;
        }
    }
    __syncthreads();

    // ---- fused local scan: per-(chunk, col); write fp16 states + carries -
    #pragma unroll
    for (int it = 0; it < 4; ++it) {
        int item = tid + it * 256;
        int cl = item & 127;
        int chunk = item >> 7;                        // 0..7
        int n = n0 + cl;
        float f = __ldg(&freq[n]);
        float dmp = __ldg(&damp[n]);
        float w2 = (TWO_PI * f) * (TWO_PI * f);
        const float* col = sf + cl * 129 + chunk * LCH;
        int gchunk = blockIdx.y * 8 + chunk;
        __half* st = g_state + (size_t)gchunk * LCH * NSZ + n;
        float s = 0.0f, v = 0.0f;
        #pragma unroll
        for (int k = 0; k < LCH; ++k) {
            float accel = fmaf(-w2, s, fmaf(-dmp, v, col[k]));
            v = fmaf(accel, DT, v);
            s = fmaf(v, DT, s);
            st[(size_t)k * NSZ] = __float2half_rn(s);
        }
        g_cs[(size_t)gchunk * NSZ + n] = s;
        g_cv[(size_t)gchunk * NSZ + n] = v;
    }
}

// ---------------- combine L1: batched loads, register chain ---------------
__global__ __launch_bounds__(256) void combine1_kernel(const float* __restrict__ freq,
                                                       const float* __restrict__ damp) {
    int idx = blockIdx.x * 256 + threadIdx.x;
    int n = idx & (NSZ - 1);
    int g = idx >> 12;
    float f = freq[n], dmp = damp[n];
    float w2 = (TWO_PI * f) * (TWO_PI * f);
    float e00, e01, e10, e11;
    m_pow2(w2, dmp, 4, e00, e01, e10, e11);     // E = M^16

    const size_t base = (size_t)(g * GSZ) * NSZ + n;

    // preload all carries (independent addresses -> full MLP)
    float cs[GSZ], cv[GSZ];
    #pragma unroll
    for (int k = 0; k < GSZ; ++k) {
        cs[k] = g_cs[base + (size_t)k * NSZ];
        cv[k] = g_cv[base + (size_t)k * NSZ];
    }
    // register-only chain, record prefixes
    float zs[GSZ], zv[GSZ];
    float sz = 0.0f, vz = 0.0f;
    #pragma unroll
    for (int k = 0; k < GSZ; ++k) {
        zs[k] = sz; zv[k] = vz;
        float ns = e00 * sz + e01 * vz + cs[k];
        float nv = e10 * sz + e11 * vz + cv[k];
        sz = ns; vz = nv;
    }
    #pragma unroll
    for (int k = 0; k < GSZ; ++k) {
        g_zs[base + (size_t)k * NSZ] = zs[k];
        g_zv[base + (size_t)k * NSZ] = zv[k];
    }
    g_Cs[(size_t)g * NSZ + n] = sz;
    g_Cv[(size_t)g * NSZ + n] = vz;
}

// ---------------- combine L2: batched loads, register chain ---------------
__global__ __launch_bounds__(256) void combine2_kernel(const float* __restrict__ freq,
                                                       const float* __restrict__ damp) {
    int n = blockIdx.x * 256 + threadIdx.x;
    float f = freq[n], dmp = damp[n];
    float w2 = (TWO_PI * f) * (TWO_PI * f);
    float e00, e01, e10, e11;
    m_pow2(w2, dmp, 8, e00, e01, e10, e11);     // E_grp = M^256

    float cs[NGRP], cv[NGRP];
    #pragma unroll
    for (int g = 0; g < NGRP; ++g) {
        cs[g] = g_Cs[(size_t)g * NSZ + n];
        cv[g] = g_Cv[(size_t)g * NSZ + n];
    }
    float zs[NGRP], zv[NGRP];
    float sz = 0.0f, vz = 0.0f;
    #pragma unroll
    for (int g = 0; g < NGRP; ++g) {
        zs[g] = sz; zv[g] = vz;
        float ns = e00 * sz + e01 * vz + cs[g];
        float nv = e10 * sz + e11 * vz + cv[g];
        sz = ns; vz = nv;
    }
    #pragma unroll
    for (int g = 0; g < NGRP; ++g) {
        g_GZs[(size_t)g * NSZ + n] = zs[g];
        g_GZv[(size_t)g * NSZ + n] = zv[g];
    }
}

// ---------------- fixup: out = clip(local + hom(z) + osc) -----------------
__global__ __launch_bounds__(256) void fixup_kernel(const float* __restrict__ freq,
                                                    const float* __restrict__ damp,
                                                    const float* __restrict__ amp,
                                                    const float* __restrict__ phase,
                                                    float* __restrict__ out) {
    int c4 = blockIdx.x * 256 + threadIdx.x;   // 0..NSZ/4-1
    int j = blockIdx.y;                        // chunk 0..255
    int g = j >> 4, kk = j & 15;
    int n = c4 * 4;
    float4 f4 = *reinterpret_cast<const float4*>(freq + n);
    float4 d4 = *reinterpret_cast<const float4*>(damp + n);
    float4 a4 = *reinterpret_cast<const float4*>(amp + n);
    float4 p4 = *reinterpret_cast<const float4*>(phase + n);

    float w2[4] = {(TWO_PI * f4.x) * (TWO_PI * f4.x), (TWO_PI * f4.y) * (TWO_PI * f4.y),
                   (TWO_PI * f4.z) * (TWO_PI * f4.z), (TWO_PI * f4.w) * (TWO_PI * f4.w)};
    float dm[4] = {d4.x, d4.y, d4.z, d4.w};
    float osc[4];
    osc[0] = a4.x * sinf(fmaf(TWO_PI * f4.x, DT, p4.x));
    osc[1] = a4.y * sinf(fmaf(TWO_PI * f4.y, DT, p4.y));
    osc[2] = a4.z * sinf(fmaf(TWO_PI * f4.z, DT, p4.z));
    osc[3] = a4.w * sinf(fmaf(TWO_PI * f4.w, DT, p4.w));

    float4 lzs = *reinterpret_cast<const float4*>(g_zs + (size_t)j * NSZ + n);
    float4 lzv = *reinterpret_cast<const float4*>(g_zv + (size_t)j * NSZ + n);
    float4 Zs4 = *reinterpret_cast<const float4*>(g_GZs + (size_t)g * NSZ + n);
    float4 Zv4 = *reinterpret_cast<const float4*>(g_GZv + (size_t)g * NSZ + n);
    float lzsa[4] = {lzs.x, lzs.y, lzs.z, lzs.w};
    float lzva[4] = {lzv.x, lzv.y, lzv.z, lzv.w};
    float Zsa[4] = {Zs4.x, Zs4.y, Zs4.z, Zs4.w};
    float Zva[4] = {Zv4.x, Zv4.y, Zv4.z, Zv4.w};

    // z_j = E^kk Z_g + lz (state/vel entering this chunk)
    float s[4], v[4];
    #pragma unroll
    for (int l = 0; l < 4; ++l) {
        float e00, e01, e10, e11;
        m_pow2(w2[l], dm[l], 4, e00, e01, e10, e11);   // E = M^16
        float us = Zsa[l], uv = Zva[l];
        for (int t = 0; t < kk; ++t) {
            float ns = e00 * us + e01 * uv;
            float nv = e10 * us + e11 * uv;
            us = ns; uv = nv;
        }
        s[l] = lzsa[l] + us;
        v[l] = lzva[l] + uv;
    }

    // row stride in uint2 units: NSZ halves = NSZ/4 uint2
    const uint2* sp = reinterpret_cast<const uint2*>(g_state + (size_t)j * LCH * NSZ + n);
    float4* op = reinterpret_cast<float4*>(out + (size_t)j * LCH * NSZ + n);
    #pragma unroll
    for (int k = 0; k < LCH; ++k) {
        uint2 lraw = sp[(size_t)k * (NSZ / 4)];
        __half2 h0 = *reinterpret_cast<__half2*>(&lraw.x);
        __half2 h1 = *reinterpret_cast<__half2*>(&lraw.y);
        float la[4] = {__low2float(h0), __high2float(h0), __low2float(h1), __high2float(h1)};
        float o[4];
        #pragma unroll
        for (int l = 0; l < 4; ++l) {
            float accel = fmaf(-w2[l], s[l], -dm[l] * v[l]);   // homogeneous step
            v[l] = fmaf(accel, DT, v[l]);
            s[l] = fmaf(v[l], DT, s[l]);
            o[l] = fminf(1.0f, fmaxf(-1.0f, la[l] + s[l] + osc[l]));
        }
        op[(size_t)k * (NSZ / 4)] = make_float4(o[0], o[1], o[2], o[3]);
    }
}

// ---------------------------------------------------------------------------
extern "C" void kernel_launch(void* const* d_in, const int* in_sizes, int n_in,
                              void* d_out, int out_size)
{
    const float* x     = (const float*)d_in[0];
    const float* W     = (const float*)d_in[1];
    const float* b     = (const float*)d_in[2];
    const float* amp   = (const float*)d_in[3];
    const float* freq  = (const float*)d_in[4];
    const float* phase = (const float*)d_in[5];
    const float* damp  = (const float*)d_in[6];
    float* out = (float*)d_out;
    (void)in_sizes; (void)n_in; (void)out_size;

    static bool attr_done = false;
    if (!attr_done) {
        cudaFuncSetAttribute(gemm_f16_kernel,
                             cudaFuncAttributeMaxDynamicSharedMemorySize, SMEM_BYTES);
        attr_done = true;
    }

    // 1. convert both operands to fp16 (single merged kernel, 8 elems/thread)
    cvt_kernel<<<(int)(((size_t)BSZ * DSZ + (size_t)NSZ * DSZ) / 8 / 256), 256>>>(x, W);

    // 2. fp16 GEMM -> fp16 local states + fp32 chunk carries (fused scan)
    dim3 ggrid(NSZ / GBN, BSZ / GBM);
    gemm_f16_kernel<<<ggrid, 256, SMEM_BYTES>>>(b, freq, damp);

    // 3. hierarchical combine (register chains, batched loads)
    combine1_kernel<<<NGRP * NSZ / 256, 256>>>(freq, damp);
    combine2_kernel<<<NSZ / 256, 256>>>(freq, damp);

    // 4. fixup: add homogeneous correction + oscillator, clip, write out
    dim3 sgrid(NSZ / 4 / 256, CCH);
    fixup_kernel<<<sgrid, 256>>>(freq, damp, amp, phase, out);
}

// round 16
// speedup vs baseline: 1.4431x; 1.0299x over previous
#include <cuda_runtime.h>
#include <cuda_fp16.h>
#include <math.h>
#include <stdint.h>

#define DT 0.01f
#define TWO_PI 6.28318530717958647692f

#define BSZ 4096
#define DSZ 2048
#define NSZ 4096

// scan chunking: 256 chunks of 16 rows; chunks grouped 16x16 for combine
#define CCH 256
#define LCH (BSZ / CCH)   // 16
#define NGRP 16
#define GSZ  16

// GEMM tiling
#define GBM 128
#define GBN 128
#define GBK 32
#define ROWB 80
#define TILEB (128 * ROWB)
#define STAGEB (2 * TILEB)
#define NSTG 3
#define KITERS (DSZ / GBK)
#define PIPE_BYTES (NSTG * STAGEB)        // 61440
#define EPI_BYTES (128 * 129 * 4)         // 66048
#define SMEM_BYTES (EPI_BYTES > PIPE_BYTES ? EPI_BYTES : PIPE_BYTES)

// ---------------- static device scratch (no allocations allowed) -----------
__device__ __half g_Ah[(size_t)BSZ * DSZ];
__device__ __half g_Wh[(size_t)NSZ * DSZ];
__device__ __half g_state[(size_t)BSZ * NSZ];                        // fp16 local states
__device__ float g_cs[(size_t)CCH * NSZ], g_cv[(size_t)CCH * NSZ];   // chunk carries
__device__ float g_zs[(size_t)CCH * NSZ], g_zv[(size_t)CCH * NSZ];   // local offsets lz
__device__ float g_Cs[(size_t)NGRP * NSZ], g_Cv[(size_t)NGRP * NSZ]; // group carries
__device__ float g_GZs[(size_t)NGRP * NSZ], g_GZv[(size_t)NGRP * NSZ]; // group prefixes

// ---------------- helpers --------------------------------------------------
__device__ __forceinline__ uint32_t smem_u32(const void* p) {
    uint32_t a;
    asm("{ .reg .u64 t; cvta.to.shared.u64 t, %1; cvt.u32.u64 %0, t; }" : "=r"(a) : "l"(p));
    return a;
}
__device__ __forceinline__ void cp16(uint32_t dst, const void* src) {
    asm volatile("cp.async.cg.shared.global [%0], [%1], 16;\n" :: "r"(dst), "l"(src));
}
__device__ __forceinline__ void ldsm_x4(uint32_t* r, uint32_t addr) {
    asm volatile("ldmatrix.sync.aligned.m8n8.x4.shared.b16 {%0,%1,%2,%3}, [%4];"
                 : "=r"(r[0]), "=r"(r[1]), "=r"(r[2]), "=r"(r[3]) : "r"(addr));
}
__device__ __forceinline__ void mma_f16(float* d, const uint32_t* a, const uint32_t* b) {
    asm volatile(
        "mma.sync.aligned.m16n8k16.row.col.f32.f16.f16.f32 "
        "{%0,%1,%2,%3}, {%4,%5,%6,%7}, {%8,%9}, {%0,%1,%2,%3};"
        : "+f"(d[0]), "+f"(d[1]), "+f"(d[2]), "+f"(d[3])
        : "r"(a[0]), "r"(a[1]), "r"(a[2]), "r"(a[3]), "r"(b[0]), "r"(b[1]));
}
// one-step transition matrix, then p squarings -> M^(2^p)
__device__ __forceinline__ void m_pow2(float w2, float dmp, int p,
                                       float& b00, float& b01, float& b10, float& b11) {
    b00 = 1.0f - w2 * DT * DT;
    b01 = DT * (1.0f - dmp * DT);
    b10 = -w2 * DT;
    b11 = 1.0f - dmp * DT;
    for (int q = 0; q < p; ++q) {
        float s00 = b00 * b00 + b01 * b10, s01 = b00 * b01 + b01 * b11;
        float s10 = b10 * b00 + b11 * b10, s11 = b10 * b01 + b11 * b11;
        b00 = s00; b01 = s01; b10 = s10; b11 = s11;
    }
}

// ---------------- merged convert kernel: fp32 -> fp16, 16 elems/thread ----
__global__ __launch_bounds__(256) void cvt_kernel(const float* __restrict__ x,
                                                  const float* __restrict__ W) {
    const size_t NA16 = (size_t)BSZ * DSZ / 16;
    size_t i = (size_t)blockIdx.x * 256 + threadIdx.x;
    const float4* src;
    uint4* dst;
    size_t j;
    if (i < NA16) {
        src = reinterpret_cast<const float4*>(x);
        dst = reinterpret_cast<uint4*>(g_Ah);
        j = i;
    } else {
        src = reinterpret_cast<const float4*>(W);
        dst = reinterpret_cast<uint4*>(g_Wh);
        j = i - NA16;
    }
    #pragma unroll
    for (int h = 0; h < 2; ++h) {
        float4 a0 = src[4 * j + 2 * h];
        float4 a1 = src[4 * j + 2 * h + 1];
        __half2 h0 = __floats2half2_rn(a0.x, a0.y);
        __half2 h1 = __floats2half2_rn(a0.z, a0.w);
        __half2 h2 = __floats2half2_rn(a1.x, a1.y);
        __half2 h3 = __floats2half2_rn(a1.z, a1.w);
        uint4 o;
        o.x = *reinterpret_cast<uint32_t*>(&h0);
        o.y = *reinterpret_cast<uint32_t*>(&h1);
        o.z = *reinterpret_cast<uint32_t*>(&h2);
        o.w = *reinterpret_cast<uint32_t*>(&h3);
        dst[2 * j + h] = o;
    }
}

// ---------------- fp16 mma.sync GEMM + fused local scan -------------------
struct Frag {
    uint32_t a[4][4];
    uint32_t b[2][4];
};

__global__ __launch_bounds__(256, 1) void gemm_f16_kernel(
    const float* __restrict__ bias,
    const float* __restrict__ freq,
    const float* __restrict__ damp) {
    extern __shared__ char smem_raw[];
    const uint32_t sbase = smem_u32(smem_raw);
    const int tid = threadIdx.x;
    const int lane = tid & 31;
    const int wid = tid >> 5;
    const int m0 = blockIdx.y * GBM;
    const int n0 = blockIdx.x * GBN;
    const int wm = (wid >> 2) * 64;
    const int wn = (wid & 3) * 32;

    float acc[4][4][4];
    #pragma unroll
    for (int mt = 0; mt < 4; ++mt)
        #pragma unroll
        for (int nt = 0; nt < 4; ++nt)
            #pragma unroll
            for (int r = 0; r < 4; ++r)
                acc[mt][nt][r] = 0.0f;

    const uint32_t a_row_off = (uint32_t)(wm + (lane & 15)) * ROWB;
    const uint32_t a_csel = ((lane >> 4) & 1) * 16;
    const uint32_t b_row_off = (uint32_t)(wn + ((lane >> 4) & 1) * 8 + (lane & 7)) * ROWB;
    const uint32_t b_csel = ((lane >> 3) & 1) * 16;

    auto load_stage = [&](int s, int buf) {
        uint32_t sb = sbase + (uint32_t)buf * STAGEB;
        int k0 = s * GBK;
        #pragma unroll
        for (int it = 0; it < 2; ++it) {
            int c = tid + it * 256;
            int row = c >> 2, c16 = c & 3;
            uint32_t soff = (uint32_t)row * ROWB + (uint32_t)c16 * 16;
            size_t gA = (size_t)(m0 + row) * DSZ + k0 + c16 * 8;
            size_t gB = (size_t)(n0 + row) * DSZ + k0 + c16 * 8;
            cp16(sb + soff, g_Ah + gA);
            cp16(sb + TILEB + soff, g_Wh + gB);
        }
    };

    auto load_frags = [&](Frag& f, uint32_t sb, int ks) {
        const uint32_t acol = (uint32_t)(ks * 32) + a_csel;
        const uint32_t bcol = (uint32_t)(ks * 32) + b_csel;
        #pragma unroll
        for (int mt = 0; mt < 4; ++mt)
            ldsm_x4(f.a[mt], sb + a_row_off + (uint32_t)(mt * 16) * ROWB + acol);
        #pragma unroll
        for (int p = 0; p < 2; ++p)
            ldsm_x4(f.b[p], sb + TILEB + b_row_off + (uint32_t)(p * 16) * ROWB + bcol);
    };

    auto mma_all = [&](const Frag& f) {
        #pragma unroll
        for (int mt = 0; mt < 4; ++mt)
            #pragma unroll
            for (int p = 0; p < 2; ++p)
                #pragma unroll
                for (int h = 0; h < 2; ++h)
                    mma_f16(acc[mt][p * 2 + h], f.a[mt], &f.b[p][h * 2]);
    };

    load_stage(0, 0);
    asm volatile("cp.async.commit_group;\n" ::: "memory");
    load_stage(1, 1);
    asm volatile("cp.async.commit_group;\n" ::: "memory");
    asm volatile("cp.async.wait_group 1;\n" ::: "memory");
    __syncthreads();

    Frag fa, fb;
    load_frags(fa, sbase, 0);

    for (int s = 0; s < KITERS; ++s) {
        const uint32_t sb_cur = sbase + (uint32_t)(s % NSTG) * STAGEB;
        if (s + 2 < KITERS) {
            load_stage(s + 2, (s + 2) % NSTG);
            asm volatile("cp.async.commit_group;\n" ::: "memory");
        }
        load_frags(fb, sb_cur, 1);
        mma_all(fa);

        if (s + 1 < KITERS) {
            if (s + 2 < KITERS)
                asm volatile("cp.async.wait_group 1;\n" ::: "memory");
            else
                asm volatile("cp.async.wait_group 0;\n" ::: "memory");
            __syncthreads();
            load_frags(fa, sbase + (uint32_t)((s + 1) % NSTG) * STAGEB, 0);
        }
        mma_all(fb);
    }

    // ---- epilogue: bias, stage tile into smem ----------------------------
    __syncthreads();
    float* sf = reinterpret_cast<float*>(smem_raw);   // [col * 129 + row]

    #pragma unroll
    for (int nt = 0; nt < 4; ++nt) {
        int cl = wn + nt * 8 + (lane & 3) * 2;
        int c = n0 + cl;
        float b0 = __ldg(&bias[c]);
        float b1 = __ldg(&bias[c + 1]);
        #pragma unroll
        for (int mt = 0; mt < 4; ++mt) {
            int rl = wm + mt * 16 + (lane >> 2);
            sf[cl * 129 + rl] = acc[mt][nt][0] + b0;
            sf[(cl + 1) * 129 + rl] = acc[mt][nt][1] + b1;
            sf[cl * 129 + rl + 8] = acc[mt][nt][2] + b0;
            sf[(cl + 1) * 129 + rl + 8] = acc[mt][nt][3] + b1;
        }
    }
    __syncthreads();

    // ---- fused local scan: per-(chunk, col); write fp16 states + carries -
    #pragma unroll
    for (int it = 0; it < 4; ++it) {
        int item = tid + it * 256;
        int cl = item & 127;
        int chunk = item >> 7;                        // 0..7
        int n = n0 + cl;
        float f = __ldg(&freq[n]);
        float dmp = __ldg(&damp[n]);
        float w2 = (TWO_PI * f) * (TWO_PI * f);
        const float* col = sf + cl * 129 + chunk * LCH;
        int gchunk = blockIdx.y * 8 + chunk;
        __half* st = g_state + (size_t)gchunk * LCH * NSZ + n;
        float s = 0.0f, v = 0.0f;
        #pragma unroll
        for (int k = 0; k < LCH; ++k) {
            float accel = fmaf(-w2, s, fmaf(-dmp, v, col[k]));
            v = fmaf(accel, DT, v);
            s = fmaf(v, DT, s);
            st[(size_t)k * NSZ] = __float2half_rn(s);
        }
        g_cs[(size_t)gchunk * NSZ + n] = s;
        g_cv[(size_t)gchunk * NSZ + n] = v;
    }
}

// ---------------- combine L1: batched loads, register chain ---------------
__global__ __launch_bounds__(256) void combine1_kernel(const float* __restrict__ freq,
                                                       const float* __restrict__ damp) {
    int idx = blockIdx.x * 256 + threadIdx.x;
    int n = idx & (NSZ - 1);
    int g = idx >> 12;
    float f = freq[n], dmp = damp[n];
    float w2 = (TWO_PI * f) * (TWO_PI * f);
    float e00, e01, e10, e11;
    m_pow2(w2, dmp, 4, e00, e01, e10, e11);     // E = M^16

    const size_t base = (size_t)(g * GSZ) * NSZ + n;

    float cs[GSZ], cv[GSZ];
    #pragma unroll
    for (int k = 0; k < GSZ; ++k) {
        cs[k] = g_cs[base + (size_t)k * NSZ];
        cv[k] = g_cv[base + (size_t)k * NSZ];
    }
    float zs[GSZ], zv[GSZ];
    float sz = 0.0f, vz = 0.0f;
    #pragma unroll
    for (int k = 0; k < GSZ; ++k) {
        zs[k] = sz; zv[k] = vz;
        float ns = e00 * sz + e01 * vz + cs[k];
        float nv = e10 * sz + e11 * vz + cv[k];
        sz = ns; vz = nv;
    }
    #pragma unroll
    for (int k = 0; k < GSZ; ++k) {
        g_zs[base + (size_t)k * NSZ] = zs[k];
        g_zv[base + (size_t)k * NSZ] = zv[k];
    }
    g_Cs[(size_t)g * NSZ + n] = sz;
    g_Cv[(size_t)g * NSZ + n] = vz;
}

// ---------------- combine L2: batched loads, register chain ---------------
__global__ __launch_bounds__(256) void combine2_kernel(const float* __restrict__ freq,
                                                       const float* __restrict__ damp) {
    int n = blockIdx.x * 256 + threadIdx.x;
    float f = freq[n], dmp = damp[n];
    float w2 = (TWO_PI * f) * (TWO_PI * f);
    float e00, e01, e10, e11;
    m_pow2(w2, dmp, 8, e00, e01, e10, e11);     // E_grp = M^256

    float cs[NGRP], cv[NGRP];
    #pragma unroll
    for (int g = 0; g < NGRP; ++g) {
        cs[g] = g_Cs[(size_t)g * NSZ + n];
        cv[g] = g_Cv[(size_t)g * NSZ + n];
    }
    float zs[NGRP], zv[NGRP];
    float sz = 0.0f, vz = 0.0f;
    #pragma unroll
    for (int g = 0; g < NGRP; ++g) {
        zs[g] = sz; zv[g] = vz;
        float ns = e00 * sz + e01 * vz + cs[g];
        float nv = e10 * sz + e11 * vz + cv[g];
        sz = ns; vz = nv;
    }
    #pragma unroll
    for (int g = 0; g < NGRP; ++g) {
        g_GZs[(size_t)g * NSZ + n] = zs[g];
        g_GZv[(size_t)g * NSZ + n] = zv[g];
    }
}

// ---------------- fixup: out = clip(local + hom(z) + osc), 8 cols/thread --
__global__ __launch_bounds__(256) void fixup_kernel(const float* __restrict__ freq,
                                                    const float* __restrict__ damp,
                                                    const float* __restrict__ amp,
                                                    const float* __restrict__ phase,
                                                    float* __restrict__ out) {
    int c8 = blockIdx.x * 256 + threadIdx.x;   // 0..NSZ/8-1
    int j = blockIdx.y;                        // chunk 0..255
    int g = j >> 4, kk = j & 15;
    int n = c8 * 8;

    float w2[8], dm[8], osc[8], s[8], v[8];
    #pragma unroll
    for (int h = 0; h < 2; ++h) {
        float4 f4 = *reinterpret_cast<const float4*>(freq + n + 4 * h);
        float4 d4 = *reinterpret_cast<const float4*>(damp + n + 4 * h);
        float4 a4 = *reinterpret_cast<const float4*>(amp + n + 4 * h);
        float4 p4 = *reinterpret_cast<const float4*>(phase + n + 4 * h);
        float fa[4] = {f4.x, f4.y, f4.z, f4.w};
        float da[4] = {d4.x, d4.y, d4.z, d4.w};
        float aa[4] = {a4.x, a4.y, a4.z, a4.w};
        float pa[4] = {p4.x, p4.y, p4.z, p4.w};
        #pragma unroll
        for (int q = 0; q < 4; ++q) {
            int l = h * 4 + q;
            w2[l] = (TWO_PI * fa[q]) * (TWO_PI * fa[q]);
            dm[l] = da[q];
            osc[l] = aa[q] * sinf(fmaf(TWO_PI * fa[q], DT, pa[q]));
        }
    }

    #pragma unroll
    for (int h = 0; h < 2; ++h) {
        float4 lzs = *reinterpret_cast<const float4*>(g_zs + (size_t)j * NSZ + n + 4 * h);
        float4 lzv = *reinterpret_cast<const float4*>(g_zv + (size_t)j * NSZ + n + 4 * h);
        float4 Zs4 = *reinterpret_cast<const float4*>(g_GZs + (size_t)g * NSZ + n + 4 * h);
        float4 Zv4 = *reinterpret_cast<const float4*>(g_GZv + (size_t)g * NSZ + n + 4 * h);
        float lzsa[4] = {lzs.x, lzs.y, lzs.z, lzs.w};
        float lzva[4] = {lzv.x, lzv.y, lzv.z, lzv.w};
        float Zsa[4] = {Zs4.x, Zs4.y, Zs4.z, Zs4.w};
        float Zva[4] = {Zv4.x, Zv4.y, Zv4.z, Zv4.w};
        #pragma unroll
        for (int q = 0; q < 4; ++q) {
            int l = h * 4 + q;
            float e00, e01, e10, e11;
            m_pow2(w2[l], dm[l], 4, e00, e01, e10, e11);   // E = M^16
            float us = Zsa[q], uv = Zva[q];
            for (int t = 0; t < kk; ++t) {
                float ns = e00 * us + e01 * uv;
                float nv = e10 * us + e11 * uv;
                us = ns; uv = nv;
            }
            s[l] = lzsa[q] + us;
            v[l] = lzva[q] + uv;
        }
    }

    // state row stride: NSZ halves = NSZ/8 uint4 (8 halves per uint4)
    const uint4* sp = reinterpret_cast<const uint4*>(g_state + (size_t)j * LCH * NSZ + n);
    float4* op = reinterpret_cast<float4*>(out + (size_t)j * LCH * NSZ + n);
    #pragma unroll
    for (int k = 0; k < LCH; ++k) {
        uint4 lraw = sp[(size_t)k * (NSZ / 8)];
        __half2 hh[4];
        hh[0] = *reinterpret_cast<__half2*>(&lraw.x);
        hh[1] = *reinterpret_cast<__half2*>(&lraw.y);
        hh[2] = *reinterpret_cast<__half2*>(&lraw.z);
        hh[3] = *reinterpret_cast<__half2*>(&lraw.w);
        float o[8];
        #pragma unroll
        for (int l = 0; l < 8; ++l) {
            float la = (l & 1) ? __high2float(hh[l >> 1]) : __low2float(hh[l >> 1]);
            float accel = fmaf(-w2[l], s[l], -dm[l] * v[l]);   // homogeneous step
            v[l] = fmaf(accel, DT, v[l]);
            s[l] = fmaf(v[l], DT, s[l]);
            o[l] = fminf(1.0f, fmaxf(-1.0f, la + s[l] + osc[l]));
        }
        op[(size_t)k * (NSZ / 4)] = make_float4(o[0], o[1], o[2], o[3]);
        op[(size_t)k * (NSZ / 4) + 1] = make_float4(o[4], o[5], o[6], o[7]);
    }
}

// ---------------------------------------------------------------------------
extern "C" void kernel_launch(void* const* d_in, const int* in_sizes, int n_in,
                              void* d_out, int out_size)
{
    const float* x     = (const float*)d_in[0];
    const float* W     = (const float*)d_in[1];
    const float* b     = (const float*)d_in[2];
    const float* amp   = (const float*)d_in[3];
    const float* freq  = (const float*)d_in[4];
    const float* phase = (const float*)d_in[5];
    const float* damp  = (const float*)d_in[6];
    float* out = (float*)d_out;
    (void)in_sizes; (void)n_in; (void)out_size;

    static bool attr_done = false;
    if (!attr_done) {
        cudaFuncSetAttribute(gemm_f16_kernel,
                             cudaFuncAttributeMaxDynamicSharedMemorySize, SMEM_BYTES);
        attr_done = true;
    }

    // 1. convert both operands to fp16 (merged kernel, 16 elems/thread)
    cvt_kernel<<<(int)(((size_t)BSZ * DSZ + (size_t)NSZ * DSZ) / 16 / 256), 256>>>(x, W);

    // 2. fp16 GEMM -> fp16 local states + fp32 chunk carries (fused scan)
    dim3 ggrid(NSZ / GBN, BSZ / GBM);
    gemm_f16_kernel<<<ggrid, 256, SMEM_BYTES>>>(b, freq, damp);

    // 3. hierarchical combine (register chains, batched loads)
    combine1_kernel<<<NGRP * NSZ / 256, 256>>>(freq, damp);
    combine2_kernel<<<NSZ / 256, 256>>>(freq, damp);

    // 4. fixup: add homogeneous correction + oscillator, clip, write out
    dim3 sgrid(NSZ / 8 / 256, CCH);
    fixup_kernel<<<sgrid, 256>>>(freq, damp, amp, phase, out);
}

// round 17
// speedup vs baseline: 1.4791x; 1.0249x over previous
#include <cuda_runtime.h>
#include <cuda_fp16.h>
#include <math.h>
#include <stdint.h>

#define DT 0.01f
#define TWO_PI 6.28318530717958647692f

#define BSZ 4096
#define DSZ 2048
#define NSZ 4096

// scan chunking: 256 chunks of 16 rows; chunks grouped 16x16 for combine
#define CCH 256
#define LCH (BSZ / CCH)   // 16
#define NGRP 16
#define GSZ  16

// GEMM tiling
#define GBM 128
#define GBN 128
#define GBK 32
#define ROWB 80
#define TILEB (128 * ROWB)
#define STAGEB (2 * TILEB)
#define NSTG 3
#define KITERS (DSZ / GBK)
#define PIPE_BYTES (NSTG * STAGEB)        // 61440
#define EPI_BYTES (128 * 129 * 4)         // 66048
#define SMEM_BYTES (EPI_BYTES > PIPE_BYTES ? EPI_BYTES : PIPE_BYTES)

// ---------------- static device scratch (no allocations allowed) -----------
__device__ __half g_Ah[(size_t)BSZ * DSZ];
__device__ __half g_Wh[(size_t)NSZ * DSZ];
__device__ __half g_state[(size_t)BSZ * NSZ];                        // fp16 local states
__device__ float g_cs[(size_t)CCH * NSZ], g_cv[(size_t)CCH * NSZ];   // chunk carries
__device__ float g_zs[(size_t)CCH * NSZ], g_zv[(size_t)CCH * NSZ];   // local offsets lz
__device__ float g_Cs[(size_t)NGRP * NSZ], g_Cv[(size_t)NGRP * NSZ]; // group carries
__device__ float g_GZs[(size_t)NGRP * NSZ], g_GZv[(size_t)NGRP * NSZ]; // group prefixes

// ---------------- helpers --------------------------------------------------
__device__ __forceinline__ uint32_t smem_u32(const void* p) {
    uint32_t a;
    asm("{ .reg .u64 t; cvta.to.shared.u64 t, %1; cvt.u32.u64 %0, t; }" : "=r"(a) : "l"(p));
    return a;
}
__device__ __forceinline__ void cp16(uint32_t dst, const void* src) {
    asm volatile("cp.async.cg.shared.global [%0], [%1], 16;\n" :: "r"(dst), "l"(src));
}
__device__ __forceinline__ void ldsm_x4(uint32_t* r, uint32_t addr) {
    asm volatile("ldmatrix.sync.aligned.m8n8.x4.shared.b16 {%0,%1,%2,%3}, [%4];"
                 : "=r"(r[0]), "=r"(r[1]), "=r"(r[2]), "=r"(r[3]) : "r"(addr));
}
__device__ __forceinline__ void mma_f16(float* d, const uint32_t* a, const uint32_t* b) {
    asm volatile(
        "mma.sync.aligned.m16n8k16.row.col.f32.f16.f16.f32 "
        "{%0,%1,%2,%3}, {%4,%5,%6,%7}, {%8,%9}, {%0,%1,%2,%3};"
        : "+f"(d[0]), "+f"(d[1]), "+f"(d[2]), "+f"(d[3])
        : "r"(a[0]), "r"(a[1]), "r"(a[2]), "r"(a[3]), "r"(b[0]), "r"(b[1]));
}
// one-step transition matrix, then p squarings -> M^(2^p)
__device__ __forceinline__ void m_pow2(float w2, float dmp, int p,
                                       float& b00, float& b01, float& b10, float& b11) {
    b00 = 1.0f - w2 * DT * DT;
    b01 = DT * (1.0f - dmp * DT);
    b10 = -w2 * DT;
    b11 = 1.0f - dmp * DT;
    for (int q = 0; q < p; ++q) {
        float s00 = b00 * b00 + b01 * b10, s01 = b00 * b01 + b01 * b11;
        float s10 = b10 * b00 + b11 * b10, s11 = b10 * b01 + b11 * b11;
        b00 = s00; b01 = s01; b10 = s10; b11 = s11;
    }
}

// ---------------- merged convert kernel: fp32 -> fp16, 16 elems/thread ----
// __ldcs: x/W are single-use here (GEMM reads g_Ah/g_Wh) -> evict-first,
// preserving L2 for the fp16 operands the GEMM re-reads 32x.
__global__ __launch_bounds__(256) void cvt_kernel(const float* __restrict__ x,
                                                  const float* __restrict__ W) {
    const size_t NA16 = (size_t)BSZ * DSZ / 16;
    size_t i = (size_t)blockIdx.x * 256 + threadIdx.x;
    const float4* src;
    uint4* dst;
    size_t j;
    if (i < NA16) {
        src = reinterpret_cast<const float4*>(x);
        dst = reinterpret_cast<uint4*>(g_Ah);
        j = i;
    } else {
        src = reinterpret_cast<const float4*>(W);
        dst = reinterpret_cast<uint4*>(g_Wh);
        j = i - NA16;
    }
    #pragma unroll
    for (int h = 0; h < 2; ++h) {
        float4 a0 = __ldcs(&src[4 * j + 2 * h]);
        float4 a1 = __ldcs(&src[4 * j + 2 * h + 1]);
        __half2 h0 = __floats2half2_rn(a0.x, a0.y);
        __half2 h1 = __floats2half2_rn(a0.z, a0.w);
        __half2 h2 = __floats2half2_rn(a1.x, a1.y);
        __half2 h3 = __floats2half2_rn(a1.z, a1.w);
        uint4 o;
        o.x = *reinterpret_cast<uint32_t*>(&h0);
        o.y = *reinterpret_cast<uint32_t*>(&h1);
        o.z = *reinterpret_cast<uint32_t*>(&h2);
        o.w = *reinterpret_cast<uint32_t*>(&h3);
        dst[2 * j + h] = o;
    }
}

// ---------------- fp16 mma.sync GEMM + fused local scan -------------------
struct Frag {
    uint32_t a[4][4];
    uint32_t b[2][4];
};

__global__ __launch_bounds__(256, 1) void gemm_f16_kernel(
    const float* __restrict__ bias,
    const float* __restrict__ freq,
    const float* __restrict__ damp) {
    extern __shared__ char smem_raw[];
    const uint32_t sbase = smem_u32(smem_raw);
    const int tid = threadIdx.x;
    const int lane = tid & 31;
    const int wid = tid >> 5;
    const int m0 = blockIdx.y * GBM;
    const int n0 = blockIdx.x * GBN;
    const int wm = (wid >> 2) * 64;
    const int wn = (wid & 3) * 32;

    float acc[4][4][4];
    #pragma unroll
    for (int mt = 0; mt < 4; ++mt)
        #pragma unroll
        for (int nt = 0; nt < 4; ++nt)
            #pragma unroll
            for (int r = 0; r < 4; ++r)
                acc[mt][nt][r] = 0.0f;

    const uint32_t a_row_off = (uint32_t)(wm + (lane & 15)) * ROWB;
    const uint32_t a_csel = ((lane >> 4) & 1) * 16;
    const uint32_t b_row_off = (uint32_t)(wn + ((lane >> 4) & 1) * 8 + (lane & 7)) * ROWB;
    const uint32_t b_csel = ((lane >> 3) & 1) * 16;

    auto load_stage = [&](int s, int buf) {
        uint32_t sb = sbase + (uint32_t)buf * STAGEB;
        int k0 = s * GBK;
        #pragma unroll
        for (int it = 0; it < 2; ++it) {
            int c = tid + it * 256;
            int row = c >> 2, c16 = c & 3;
            uint32_t soff = (uint32_t)row * ROWB + (uint32_t)c16 * 16;
            size_t gA = (size_t)(m0 + row) * DSZ + k0 + c16 * 8;
            size_t gB = (size_t)(n0 + row) * DSZ + k0 + c16 * 8;
            cp16(sb + soff, g_Ah + gA);
            cp16(sb + TILEB + soff, g_Wh + gB);
        }
    };

    auto load_frags = [&](Frag& f, uint32_t sb, int ks) {
        const uint32_t acol = (uint32_t)(ks * 32) + a_csel;
        const uint32_t bcol = (uint32_t)(ks * 32) + b_csel;
        #pragma unroll
        for (int mt = 0; mt < 4; ++mt)
            ldsm_x4(f.a[mt], sb + a_row_off + (uint32_t)(mt * 16) * ROWB + acol);
        #pragma unroll
        for (int p = 0; p < 2; ++p)
            ldsm_x4(f.b[p], sb + TILEB + b_row_off + (uint32_t)(p * 16) * ROWB + bcol);
    };

    auto mma_all = [&](const Frag& f) {
        #pragma unroll
        for (int mt = 0; mt < 4; ++mt)
            #pragma unroll
            for (int p = 0; p < 2; ++p)
                #pragma unroll
                for (int h = 0; h < 2; ++h)
                    mma_f16(acc[mt][p * 2 + h], f.a[mt], &f.b[p][h * 2]);
    };

    load_stage(0, 0);
    asm volatile("cp.async.commit_group;\n" ::: "memory");
    load_stage(1, 1);
    asm volatile("cp.async.commit_group;\n" ::: "memory");
    asm volatile("cp.async.wait_group 1;\n" ::: "memory");
    __syncthreads();

    Frag fa, fb;
    load_frags(fa, sbase, 0);

    for (int s = 0; s < KITERS; ++s) {
        const uint32_t sb_cur = sbase + (uint32_t)(s % NSTG) * STAGEB;
        if (s + 2 < KITERS) {
            load_stage(s + 2, (s + 2) % NSTG);
            asm volatile("cp.async.commit_group;\n" ::: "memory");
        }
        load_frags(fb, sb_cur, 1);
        mma_all(fa);

        if (s + 1 < KITERS) {
            if (s + 2 < KITERS)
                asm volatile("cp.async.wait_group 1;\n" ::: "memory");
            else
                asm volatile("cp.async.wait_group 0;\n" ::: "memory");
            __syncthreads();
            load_frags(fa, sbase + (uint32_t)((s + 1) % NSTG) * STAGEB, 0);
        }
        mma_all(fb);
    }

    // ---- epilogue: bias, stage tile into smem ----------------------------
    __syncthreads();
    float* sf = reinterpret_cast<float*>(smem_raw);   // [col * 129 + row]

    #pragma unroll
    for (int nt = 0; nt < 4; ++nt) {
        int cl = wn + nt * 8 + (lane & 3) * 2;
        int c = n0 + cl;
        float b0 = __ldg(&bias[c]);
        float b1 = __ldg(&bias[c + 1]);
        #pragma unroll
        for (int mt = 0; mt < 4; ++mt) {
            int rl = wm + mt * 16 + (lane >> 2);
            sf[cl * 129 + rl] = acc[mt][nt][0] + b0;
            sf[(cl + 1) * 129 + rl] = acc[mt][nt][1] + b1;
            sf[cl * 129 + rl + 8] = acc[mt][nt][2] + b0;
            sf[(cl + 1) * 129 + rl + 8] = acc[mt][nt][3] + b1;
        }
    }
    __syncthreads();

    // ---- fused local scan: per-(chunk, col); write fp16 states + carries -
    #pragma unroll
    for (int it = 0; it < 4; ++it) {
        int item = tid + it * 256;
        int cl = item & 127;
        int chunk = item >> 7;                        // 0..7
        int n = n0 + cl;
        float f = __ldg(&freq[n]);
        float dmp = __ldg(&damp[n]);
        float w2 = (TWO_PI * f) * (TWO_PI * f);
        const float* col = sf + cl * 129 + chunk * LCH;
        int gchunk = blockIdx.y * 8 + chunk;
        __half* st = g_state + (size_t)gchunk * LCH * NSZ + n;
        float s = 0.0f, v = 0.0f;
        #pragma unroll
        for (int k = 0; k < LCH; ++k) {
            float accel = fmaf(-w2, s, fmaf(-dmp, v, col[k]));
            v = fmaf(accel, DT, v);
            s = fmaf(v, DT, s);
            st[(size_t)k * NSZ] = __float2half_rn(s);
        }
        g_cs[(size_t)gchunk * NSZ + n] = s;
        g_cv[(size_t)gchunk * NSZ + n] = v;
    }
}

// ---------------- combine L1: batched loads, register chain ---------------
__global__ __launch_bounds__(256) void combine1_kernel(const float* __restrict__ freq,
                                                       const float* __restrict__ damp) {
    int idx = blockIdx.x * 256 + threadIdx.x;
    int n = idx & (NSZ - 1);
    int g = idx >> 12;
    float f = freq[n], dmp = damp[n];
    float w2 = (TWO_PI * f) * (TWO_PI * f);
    float e00, e01, e10, e11;
    m_pow2(w2, dmp, 4, e00, e01, e10, e11);     // E = M^16

    const size_t base = (size_t)(g * GSZ) * NSZ + n;

    float cs[GSZ], cv[GSZ];
    #pragma unroll
    for (int k = 0; k < GSZ; ++k) {
        cs[k] = g_cs[base + (size_t)k * NSZ];
        cv[k] = g_cv[base + (size_t)k * NSZ];
    }
    float zs[GSZ], zv[GSZ];
    float sz = 0.0f, vz = 0.0f;
    #pragma unroll
    for (int k = 0; k < GSZ; ++k) {
        zs[k] = sz; zv[k] = vz;
        float ns = e00 * sz + e01 * vz + cs[k];
        float nv = e10 * sz + e11 * vz + cv[k];
        sz = ns; vz = nv;
    }
    #pragma unroll
    for (int k = 0; k < GSZ; ++k) {
        g_zs[base + (size_t)k * NSZ] = zs[k];
        g_zv[base + (size_t)k * NSZ] = zv[k];
    }
    g_Cs[(size_t)g * NSZ + n] = sz;
    g_Cv[(size_t)g * NSZ + n] = vz;
}

// ---------------- combine L2: batched loads, register chain ---------------
// 64-thread blocks over 64 SMs: spreads the latency-bound chain wider.
__global__ __launch_bounds__(64) void combine2_kernel(const float* __restrict__ freq,
                                                      const float* __restrict__ damp) {
    int n = blockIdx.x * 64 + threadIdx.x;
    float f = freq[n], dmp = damp[n];
    float w2 = (TWO_PI * f) * (TWO_PI * f);
    float e00, e01, e10, e11;
    m_pow2(w2, dmp, 8, e00, e01, e10, e11);     // E_grp = M^256

    float cs[NGRP], cv[NGRP];
    #pragma unroll
    for (int g = 0; g < NGRP; ++g) {
        cs[g] = g_Cs[(size_t)g * NSZ + n];
        cv[g] = g_Cv[(size_t)g * NSZ + n];
    }
    float zs[NGRP], zv[NGRP];
    float sz = 0.0f, vz = 0.0f;
    #pragma unroll
    for (int g = 0; g < NGRP; ++g) {
        zs[g] = sz; zv[g] = vz;
        float ns = e00 * sz + e01 * vz + cs[g];
        float nv = e10 * sz + e11 * vz + cv[g];
        sz = ns; vz = nv;
    }
    #pragma unroll
    for (int g = 0; g < NGRP; ++g) {
        g_GZs[(size_t)g * NSZ + n] = zs[g];
        g_GZv[(size_t)g * NSZ + n] = zv[g];
    }
}

// ---------------- fixup: out = clip(local + hom(z) + osc), 8 cols/thread --
__global__ __launch_bounds__(256) void fixup_kernel(const float* __restrict__ freq,
                                                    const float* __restrict__ damp,
                                                    const float* __restrict__ amp,
                                                    const float* __restrict__ phase,
                                                    float* __restrict__ out) {
    int c8 = blockIdx.x * 256 + threadIdx.x;   // 0..NSZ/8-1
    int j = blockIdx.y;                        // chunk 0..255
    int g = j >> 4, kk = j & 15;
    int n = c8 * 8;

    float w2[8], dm[8], osc[8], s[8], v[8];
    #pragma unroll
    for (int h = 0; h < 2; ++h) {
        float4 f4 = *reinterpret_cast<const float4*>(freq + n + 4 * h);
        float4 d4 = *reinterpret_cast<const float4*>(damp + n + 4 * h);
        float4 a4 = *reinterpret_cast<const float4*>(amp + n + 4 * h);
        float4 p4 = *reinterpret_cast<const float4*>(phase + n + 4 * h);
        float fa[4] = {f4.x, f4.y, f4.z, f4.w};
        float da[4] = {d4.x, d4.y, d4.z, d4.w};
        float aa[4] = {a4.x, a4.y, a4.z, a4.w};
        float pa[4] = {p4.x, p4.y, p4.z, p4.w};
        #pragma unroll
        for (int q = 0; q < 4; ++q) {
            int l = h * 4 + q;
            w2[l] = (TWO_PI * fa[q]) * (TWO_PI * fa[q]);
            dm[l] = da[q];
            osc[l] = aa[q] * sinf(fmaf(TWO_PI * fa[q], DT, pa[q]));
        }
    }

    #pragma unroll
    for (int h = 0; h < 2; ++h) {
        float4 lzs = *reinterpret_cast<const float4*>(g_zs + (size_t)j * NSZ + n + 4 * h);
        float4 lzv = *reinterpret_cast<const float4*>(g_zv + (size_t)j * NSZ + n + 4 * h);
        float4 Zs4 = *reinterpret_cast<const float4*>(g_GZs + (size_t)g * NSZ + n + 4 * h);
        float4 Zv4 = *reinterpret_cast<const float4*>(g_GZv + (size_t)g * NSZ + n + 4 * h);
        float lzsa[4] = {lzs.x, lzs.y, lzs.z, lzs.w};
        float lzva[4] = {lzv.x, lzv.y, lzv.z, lzv.w};
        float Zsa[4] = {Zs4.x, Zs4.y, Zs4.z, Zs4.w};
        float Zva[4] = {Zv4.x, Zv4.y, Zv4.z, Zv4.w};
        #pragma unroll
        for (int q = 0; q < 4; ++q) {
            int l = h * 4 + q;
            float e00, e01, e10, e11;
            m_pow2(w2[l], dm[l], 4, e00, e01, e10, e11);   // E = M^16
            float us = Zsa[q], uv = Zva[q];
            for (int t = 0; t < kk; ++t) {
                float ns = e00 * us + e01 * uv;
                float nv = e10 * us + e11 * uv;
                us = ns; uv = nv;
            }
            s[l] = lzsa[q] + us;
            v[l] = lzva[q] + uv;
        }
    }

    // state row stride: NSZ halves = NSZ/8 uint4 (8 halves per uint4)
    const uint4* sp = reinterpret_cast<const uint4*>(g_state + (size_t)j * LCH * NSZ + n);
    float4* op = reinterpret_cast<float4*>(out + (size_t)j * LCH * NSZ + n);
    #pragma unroll
    for (int k = 0; k < LCH; ++k) {
        uint4 lraw = sp[(size_t)k * (NSZ / 8)];
        __half2 hh[4];
        hh[0] = *reinterpret_cast<__half2*>(&lraw.x);
        hh[1] = *reinterpret_cast<__half2*>(&lraw.y);
        hh[2] = *reinterpret_cast<__half2*>(&lraw.z);
        hh[3] = *reinterpret_cast<__half2*>(&lraw.w);
        float o[8];
        #pragma unroll
        for (int l = 0; l < 8; ++l) {
            float la = (l & 1) ? __high2float(hh[l >> 1]) : __low2float(hh[l >> 1]);
            float accel = fmaf(-w2[l], s[l], -dm[l] * v[l]);   // homogeneous step
            v[l] = fmaf(accel, DT, v[l]);
            s[l] = fmaf(v[l], DT, s[l]);
            o[l] = fminf(1.0f, fmaxf(-1.0f, la + s[l] + osc[l]));
        }
        // single-use output -> streaming store, keep g_state L2-resident
        __stcs(&op[(size_t)k * (NSZ / 4)], make_float4(o[0], o[1], o[2], o[3]));
        __stcs(&op[(size_t)k * (NSZ / 4) + 1], make_float4(o[4], o[5], o[6], o[7]));
    }
}

// ---------------------------------------------------------------------------
extern "C" void kernel_launch(void* const* d_in, const int* in_sizes, int n_in,
                              void* d_out, int out_size)
{
    const float* x     = (const float*)d_in[0];
    const float* W     = (const float*)d_in[1];
    const float* b     = (const float*)d_in[2];
    const float* amp   = (const float*)d_in[3];
    const float* freq  = (const float*)d_in[4];
    const float* phase = (const float*)d_in[5];
    const float* damp  = (const float*)d_in[6];
    float* out = (float*)d_out;
    (void)in_sizes; (void)n_in; (void)out_size;

    static bool attr_done = false;
    if (!attr_done) {
        cudaFuncSetAttribute(gemm_f16_kernel,
                             cudaFuncAttributeMaxDynamicSharedMemorySize, SMEM_BYTES);
        attr_done = true;
    }

    // 1. convert both operands to fp16 (merged kernel, 16 elems/thread)
    cvt_kernel<<<(int)(((size_t)BSZ * DSZ + (size_t)NSZ * DSZ) / 16 / 256), 256>>>(x, W);

    // 2. fp16 GEMM -> fp16 local states + fp32 chunk carries (fused scan)
    dim3 ggrid(NSZ / GBN, BSZ / GBM);
    gemm_f16_kernel<<<ggrid, 256, SMEM_BYTES>>>(b, freq, damp);

    // 3. hierarchical combine (register chains, batched loads)
    combine1_kernel<<<NGRP * NSZ / 256, 256>>>(freq, damp);
    combine2_kernel<<<NSZ / 64, 64>>>(freq, damp);

    // 4. fixup: add homogeneous correction + oscillator, clip, write out
    dim3 sgrid(NSZ / 8 / 256, CCH);
    fixup_kernel<<<sgrid, 256>>>(freq, damp, amp, phase, out);
}